// round 1
// baseline (speedup 1.0000x reference)
#include <cuda_runtime.h>
#include <math.h>

// ---------------- problem constants ----------------
static constexpr int B_   = 2;
static constexpr int S_   = 2048;
static constexpr int HID_ = 4096;
static constexpr int NH_  = 32;
static constexpr int D_   = 128;
static constexpr int G_   = 8;
static constexpr int RK_  = 256;
static constexpr int FGD_ = 256;   // fused group dim
static constexpr int FH_  = 8192;  // fused hidden dim

// ---------------- scratch (static device bss, no runtime alloc) ----------------
__device__ float g_Q   [(long long)B_ * S_ * HID_];        // 64 MB
__device__ float g_K   [(long long)B_ * S_ * HID_];        // 64 MB
__device__ float g_klat[(long long)B_ * S_ * (G_*RK_)];    // 32 MB
__device__ float g_vlat[(long long)B_ * S_ * (G_*FGD_)];   // 32 MB
__device__ float g_P   [(long long)B_ * NH_ * S_ * S_];    // 1 GiB
__device__ float g_scr [(long long)B_ * S_ * FH_];         // 128 MB

// ---------------- generic tiled SGEMM ----------------
// C[M,N] = A[M,K] * op(B)   op = B^T (TRB=true, B is [N,K]) or B (TRB=false, [K,N])
// MODE 0: plain store
// MODE 1: scores epilogue: val*scale, causal mask (col>row -> -1e30), tile early-out
// MODE 2: AV epilogue with PALU scramble store
//
// batch: z = zo*ziCount + zi ; pointer offsets zo*So + zi*Si per operand.
#define BM 128
#define BN 128
#define BK 16
#define TM 8
#define TN 8

template<int MODE, bool TRB>
__global__ void __launch_bounds__(256)
sgemm(const float* __restrict__ Ag, const float* __restrict__ Bg, float* __restrict__ Cg,
      int M, int N, int K, int lda, int ldb, int ldc,
      long long aSo, long long aSi, long long bSo, long long bSi,
      long long cSo, long long cSi, int ziCount, float scale)
{
    const int zo = blockIdx.z / ziCount;
    const int zi = blockIdx.z % ziCount;
    const float* A = Ag + zo * aSo + zi * aSi;
    const float* Bm = Bg + zo * bSo + zi * bSi;
    float* C = Cg + zo * cSo + zi * cSi;

    const int row0 = blockIdx.y * BM;
    const int col0 = blockIdx.x * BN;
    const int tid = threadIdx.x;
    const int rm = (tid >> 4) * TM;   // 0..120
    const int rn = (tid & 15) * TN;   // 0..120

    if (MODE == 1) {
        // fully-masked tile (all cols > all rows): write -1e30 and bail.
        if (col0 > row0 + BM - 1) {
            const float4 mv = make_float4(-1e30f, -1e30f, -1e30f, -1e30f);
            #pragma unroll
            for (int i = 0; i < TM; i++) {
                long long crow = (long long)(row0 + rm + i) * ldc + col0 + rn;
                *(float4*)(C + crow)     = mv;
                *(float4*)(C + crow + 4) = mv;
            }
            return;
        }
    }

    __shared__ float As[BK][BM];
    __shared__ float Bs[BK][BN];

    float acc[TM][TN];
    #pragma unroll
    for (int i = 0; i < TM; i++)
        #pragma unroll
        for (int j = 0; j < TN; j++) acc[i][j] = 0.0f;

    for (int k0 = 0; k0 < K; k0 += BK) {
        // A tile: BM x BK (store transposed into As[k][m])
        #pragma unroll
        for (int it = 0; it < 2; it++) {
            int idx = tid + it * 256;           // float4 index 0..511
            int ar = idx >> 2;                  // m 0..127
            int ac = (idx & 3) * 4;             // k 0,4,8,12
            float4 v = *(const float4*)(A + (long long)(row0 + ar) * lda + k0 + ac);
            As[ac + 0][ar] = v.x; As[ac + 1][ar] = v.y;
            As[ac + 2][ar] = v.z; As[ac + 3][ar] = v.w;
        }
        if (TRB) {
            // B tile: BN x BK from [N,K] row-major -> Bs[k][n]
            #pragma unroll
            for (int it = 0; it < 2; it++) {
                int idx = tid + it * 256;
                int br = idx >> 2;              // n 0..127
                int bc = (idx & 3) * 4;         // k
                float4 v = *(const float4*)(Bm + (long long)(col0 + br) * ldb + k0 + bc);
                Bs[bc + 0][br] = v.x; Bs[bc + 1][br] = v.y;
                Bs[bc + 2][br] = v.z; Bs[bc + 3][br] = v.w;
            }
        } else {
            // B tile: BK x BN from [K,N] row-major -> Bs[k][n] direct
            #pragma unroll
            for (int it = 0; it < 2; it++) {
                int idx = tid + it * 256;
                int br = idx >> 5;              // k 0..15
                int bc = (idx & 31) * 4;        // n
                float4 v = *(const float4*)(Bm + (long long)(k0 + br) * ldb + col0 + bc);
                *(float4*)&Bs[br][bc] = v;
            }
        }
        __syncthreads();

        #pragma unroll
        for (int kk = 0; kk < BK; kk++) {
            float a[TM], b[TN];
            #pragma unroll
            for (int i = 0; i < TM; i++) a[i] = As[kk][rm + i];
            #pragma unroll
            for (int j = 0; j < TN; j++) b[j] = Bs[kk][rn + j];
            #pragma unroll
            for (int i = 0; i < TM; i++)
                #pragma unroll
                for (int j = 0; j < TN; j++)
                    acc[i][j] = fmaf(a[i], b[j], acc[i][j]);
        }
        __syncthreads();
    }

    if (MODE == 0) {
        #pragma unroll
        for (int i = 0; i < TM; i++) {
            long long crow = (long long)(row0 + rm + i) * ldc + col0 + rn;
            *(float4*)(C + crow)     = make_float4(acc[i][0], acc[i][1], acc[i][2], acc[i][3]);
            *(float4*)(C + crow + 4) = make_float4(acc[i][4], acc[i][5], acc[i][6], acc[i][7]);
        }
    } else if (MODE == 1) {
        #pragma unroll
        for (int i = 0; i < TM; i++) {
            int gr = row0 + rm + i;
            long long crow = (long long)gr * ldc;
            #pragma unroll
            for (int j = 0; j < TN; j++) {
                int gc = col0 + rn + j;
                float v = acc[i][j] * scale;
                if (gc > gr) v = -1e30f;
                C[crow + gc] = v;
            }
        }
    } else { // MODE 2: PALU scramble store
        // row gr = hg*2048 + s ; col = f (0..255). C already offset by b,g.
        #pragma unroll
        for (int i = 0; i < TM; i++) {
            int gr = row0 + rm + i;
            int hg = gr >> 11;
            int s  = gr & 2047;
            long long base = (long long)(hg * 512 + (s >> 2)) * FH_ + (s & 3) * 2048;
            #pragma unroll
            for (int j = 0; j < TN; j += 4) {
                long long idx = base + col0 + rn + j;
                *(float4*)(C + idx) = make_float4(acc[i][j], acc[i][j+1], acc[i][j+2], acc[i][j+3]);
            }
        }
    }
}

// ---------------- RoPE (in-place on Q and K, layout (b*s, 4096)) ----------------
__global__ void rope_kernel(float* __restrict__ Q, float* __restrict__ Kb,
                            const int* __restrict__ pos_ids)
{
    const int row = blockIdx.x;            // b*S + s
    const float p = (float)pos_ids[row];
    const long long base = (long long)row * HID_;
    // 2048 (head, d<64) pairs per row
    for (int t = threadIdx.x; t < NH_ * 64; t += blockDim.x) {
        int h = t >> 6;
        int d = t & 63;
        // inv_freq = 10000^(-d/64)
        float inv = exp2f(-(float)d * (13.287712379549449f / 64.0f));
        float ang = p * inv;
        float sn, cs;
        sincosf(ang, &sn, &cs);
        int c1 = h * D_ + d;
        int c2 = c1 + 64;
        float qx = Q[base + c1], qy = Q[base + c2];
        Q[base + c1] = qx * cs - qy * sn;
        Q[base + c2] = qy * cs + qx * sn;
        float kx = Kb[base + c1], ky = Kb[base + c2];
        Kb[base + c1] = kx * cs - ky * sn;
        Kb[base + c2] = ky * cs + kx * sn;
    }
}

// ---------------- row softmax over len-2048 rows ----------------
__global__ void __launch_bounds__(256) softmax_kernel(float* __restrict__ P)
{
    const long long row = blockIdx.x;
    float* r = P + row * (long long)S_;
    const int tid = threadIdx.x;
    float v[8];
    float m = -1e38f;
    #pragma unroll
    for (int i = 0; i < 8; i++) { v[i] = r[tid + i * 256]; m = fmaxf(m, v[i]); }
    __shared__ float red[256];
    red[tid] = m; __syncthreads();
    #pragma unroll
    for (int s = 128; s > 0; s >>= 1) {
        if (tid < s) red[tid] = fmaxf(red[tid], red[tid + s]);
        __syncthreads();
    }
    m = red[0];
    __syncthreads();
    float sum = 0.0f;
    #pragma unroll
    for (int i = 0; i < 8; i++) { v[i] = expf(v[i] - m); sum += v[i]; }
    red[tid] = sum; __syncthreads();
    #pragma unroll
    for (int s = 128; s > 0; s >>= 1) {
        if (tid < s) red[tid] += red[tid + s];
        __syncthreads();
    }
    float inv = 1.0f / red[0];
    #pragma unroll
    for (int i = 0; i < 8; i++) r[tid + i * 256] = v[i] * inv;
}

// ---------------- launcher ----------------
extern "C" void kernel_launch(void* const* d_in, const int* in_sizes, int n_in,
                              void* d_out, int out_size)
{
    const float* H   = (const float*)d_in[0];
    // d_in[1] = attention_mask (pure causal -> applied analytically)
    const int*   pos = (const int*)  d_in[2];
    const float* Wq  = (const float*)d_in[3];
    const float* WVT = (const float*)d_in[4];
    const float* U   = (const float*)d_in[5];
    const float* Wv  = (const float*)d_in[6];
    const float* Wo  = (const float*)d_in[7];
    float* out = (float*)d_out;

    float *Q, *K, *klat, *vlat, *P, *scr;
    cudaGetSymbolAddress((void**)&Q,    g_Q);
    cudaGetSymbolAddress((void**)&K,    g_K);
    cudaGetSymbolAddress((void**)&klat, g_klat);
    cudaGetSymbolAddress((void**)&vlat, g_vlat);
    cudaGetSymbolAddress((void**)&P,    g_P);
    cudaGetSymbolAddress((void**)&scr,  g_scr);

    const dim3 blk(256);
    const int BS = B_ * S_;            // 4096 rows

    // 1) Q = H @ Wq^T            (4096 x 4096, K=4096)
    sgemm<0, true><<<dim3(HID_/BN, BS/BM, 1), blk>>>(
        H, Wq, Q, BS, HID_, HID_, HID_, HID_, HID_,
        0, 0, 0, 0, 0, 0, 1, 1.0f);

    // 2) k_lat = H @ WVT^T       (4096 x 2048)
    sgemm<0, true><<<dim3((G_*RK_)/BN, BS/BM, 1), blk>>>(
        H, WVT, klat, BS, G_*RK_, HID_, HID_, HID_, G_*RK_,
        0, 0, 0, 0, 0, 0, 1, 1.0f);

    // 3) v_lat = H @ Wv^T        (4096 x 2048)
    sgemm<0, true><<<dim3((G_*FGD_)/BN, BS/BM, 1), blk>>>(
        H, Wv, vlat, BS, G_*FGD_, HID_, HID_, HID_, G_*FGD_,
        0, 0, 0, 0, 0, 0, 1, 1.0f);

    // 4) K reconstruction: per (b,g): (2048 x 512) = klat_g (2048x256) @ Ug^T
    sgemm<0, true><<<dim3(512/BN, S_/BM, B_*G_), blk>>>(
        klat, U, K, S_, 512, RK_, G_*RK_, G_*RK_, HID_,
        (long long)S_*(G_*RK_), RK_,            // A: b, g offsets
        0, RK_,                                 // B (U): g offset = g*256
        (long long)S_*HID_, 512,                // C: b, g*512
        G_, 1.0f);

    // 5) RoPE on Q and K
    rope_kernel<<<BS, 256>>>(Q, K, pos);

    // 6) scores: per (b,h): (2048 x 2048) = Q_h @ K_h^T / sqrt(D), causal mask
    sgemm<1, true><<<dim3(S_/BN, S_/BM, B_*NH_), blk>>>(
        Q, K, P, S_, S_, D_, HID_, HID_, S_,
        (long long)S_*HID_, D_,                 // A: b, h*128
        (long long)S_*HID_, D_,                 // B: b, h*128
        (long long)NH_*S_*S_, (long long)S_*S_, // C: b, h
        NH_, 0.08838834764831845f);

    // 7) softmax rows
    softmax_kernel<<<B_*NH_*S_, 256>>>(P);

    // 8) AV: per (b,g): (8192 x 256) = P_g (8192x2048) @ v_lat_g (2048x256), scramble store
    sgemm<2, false><<<dim3(FGD_/BN, (4*S_)/BM, B_*G_), blk>>>(
        P, vlat, scr, 4*S_, FGD_, S_, S_, G_*FGD_, 0,
        (long long)NH_*S_*S_, (long long)4*S_*S_,  // A: b, g (4 heads contiguous)
        (long long)S_*(G_*FGD_), FGD_,             // B: b, g*256
        (long long)S_*FH_, FGD_,                   // C: b, g*256
        G_, 1.0f);

    // 9) out = scr @ Wo^T        (4096 x 4096, K=8192)
    sgemm<0, true><<<dim3(HID_/BN, BS/BM, 1), blk>>>(
        scr, Wo, out, BS, HID_, FH_, FH_, FH_, HID_,
        0, 0, 0, 0, 0, 0, 1, 1.0f);
}

// round 2
// speedup vs baseline: 1.0011x; 1.0011x over previous
#include <cuda_runtime.h>
#include <math.h>

// ---------------- problem constants ----------------
static constexpr int B_   = 2;
static constexpr int S_   = 2048;
static constexpr int HID_ = 4096;
static constexpr int NH_  = 32;
static constexpr int D_   = 128;
static constexpr int G_   = 8;
static constexpr int RK_  = 256;
static constexpr int FGD_ = 256;   // fused group dim
static constexpr int FH_  = 8192;  // fused hidden dim

// ---------------- scratch (static device bss, no runtime alloc) ----------------
__device__ float g_Q   [(long long)B_ * S_ * HID_];        // 64 MB
__device__ float g_K   [(long long)B_ * S_ * HID_];        // 64 MB
__device__ float g_klat[(long long)B_ * S_ * (G_*RK_)];    // 32 MB
__device__ float g_vlat[(long long)B_ * S_ * (G_*FGD_)];   // 32 MB
__device__ float g_P   [(long long)B_ * NH_ * S_ * S_];    // 1 GiB
__device__ float g_scr [(long long)B_ * S_ * FH_];         // 128 MB

// ---------------- generic tiled SGEMM ----------------
// C[M,N] = A[M,K] * op(B)   op = B^T (TRB=true, B is [N,K]) or B (TRB=false, [K,N])
// MODE 0: plain store
// MODE 1: scores epilogue: val*scale, causal mask (col>row -> -1e30), tile early-out
// MODE 2: AV epilogue with PALU scramble store
//
// batch: z = zo*ziCount + zi ; pointer offsets zo*So + zi*Si per operand.
#define BM 128
#define BN 128
#define BK 16
#define TM 8
#define TN 8

template<int MODE, bool TRB>
__global__ void __launch_bounds__(256)
sgemm(const float* __restrict__ Ag, const float* __restrict__ Bg, float* __restrict__ Cg,
      int M, int N, int K, int lda, int ldb, int ldc,
      long long aSo, long long aSi, long long bSo, long long bSi,
      long long cSo, long long cSi, int ziCount, float scale)
{
    const int zo = blockIdx.z / ziCount;
    const int zi = blockIdx.z % ziCount;
    const float* A = Ag + zo * aSo + zi * aSi;
    const float* Bm = Bg + zo * bSo + zi * bSi;
    float* C = Cg + zo * cSo + zi * cSi;

    const int row0 = blockIdx.y * BM;
    const int col0 = blockIdx.x * BN;
    const int tid = threadIdx.x;
    const int rm = (tid >> 4) * TM;   // 0..120
    const int rn = (tid & 15) * TN;   // 0..120

    if (MODE == 1) {
        // fully-masked tile (all cols > all rows): write -1e30 and bail.
        if (col0 > row0 + BM - 1) {
            const float4 mv = make_float4(-1e30f, -1e30f, -1e30f, -1e30f);
            #pragma unroll
            for (int i = 0; i < TM; i++) {
                long long crow = (long long)(row0 + rm + i) * ldc + col0 + rn;
                *(float4*)(C + crow)     = mv;
                *(float4*)(C + crow + 4) = mv;
            }
            return;
        }
    }

    __shared__ float As[BK][BM];
    __shared__ float Bs[BK][BN];

    float acc[TM][TN];
    #pragma unroll
    for (int i = 0; i < TM; i++)
        #pragma unroll
        for (int j = 0; j < TN; j++) acc[i][j] = 0.0f;

    for (int k0 = 0; k0 < K; k0 += BK) {
        // A tile: BM x BK (store transposed into As[k][m])
        #pragma unroll
        for (int it = 0; it < 2; it++) {
            int idx = tid + it * 256;           // float4 index 0..511
            int ar = idx >> 2;                  // m 0..127
            int ac = (idx & 3) * 4;             // k 0,4,8,12
            float4 v = *(const float4*)(A + (long long)(row0 + ar) * lda + k0 + ac);
            As[ac + 0][ar] = v.x; As[ac + 1][ar] = v.y;
            As[ac + 2][ar] = v.z; As[ac + 3][ar] = v.w;
        }
        if (TRB) {
            // B tile: BN x BK from [N,K] row-major -> Bs[k][n]
            #pragma unroll
            for (int it = 0; it < 2; it++) {
                int idx = tid + it * 256;
                int br = idx >> 2;              // n 0..127
                int bc = (idx & 3) * 4;         // k
                float4 v = *(const float4*)(Bm + (long long)(col0 + br) * ldb + k0 + bc);
                Bs[bc + 0][br] = v.x; Bs[bc + 1][br] = v.y;
                Bs[bc + 2][br] = v.z; Bs[bc + 3][br] = v.w;
            }
        } else {
            // B tile: BK x BN from [K,N] row-major -> Bs[k][n] direct
            #pragma unroll
            for (int it = 0; it < 2; it++) {
                int idx = tid + it * 256;
                int br = idx >> 5;              // k 0..15
                int bc = (idx & 31) * 4;        // n
                float4 v = *(const float4*)(Bm + (long long)(k0 + br) * ldb + col0 + bc);
                *(float4*)&Bs[br][bc] = v;
            }
        }
        __syncthreads();

        #pragma unroll
        for (int kk = 0; kk < BK; kk++) {
            float a[TM], b[TN];
            #pragma unroll
            for (int i = 0; i < TM; i++) a[i] = As[kk][rm + i];
            #pragma unroll
            for (int j = 0; j < TN; j++) b[j] = Bs[kk][rn + j];
            #pragma unroll
            for (int i = 0; i < TM; i++)
                #pragma unroll
                for (int j = 0; j < TN; j++)
                    acc[i][j] = fmaf(a[i], b[j], acc[i][j]);
        }
        __syncthreads();
    }

    if (MODE == 0) {
        #pragma unroll
        for (int i = 0; i < TM; i++) {
            long long crow = (long long)(row0 + rm + i) * ldc + col0 + rn;
            *(float4*)(C + crow)     = make_float4(acc[i][0], acc[i][1], acc[i][2], acc[i][3]);
            *(float4*)(C + crow + 4) = make_float4(acc[i][4], acc[i][5], acc[i][6], acc[i][7]);
        }
    } else if (MODE == 1) {
        #pragma unroll
        for (int i = 0; i < TM; i++) {
            int gr = row0 + rm + i;
            long long crow = (long long)gr * ldc;
            #pragma unroll
            for (int j = 0; j < TN; j++) {
                int gc = col0 + rn + j;
                float v = acc[i][j] * scale;
                if (gc > gr) v = -1e30f;
                C[crow + gc] = v;
            }
        }
    } else { // MODE 2: PALU scramble store
        // row gr = hg*2048 + s ; col = f (0..255). C already offset by b,g.
        #pragma unroll
        for (int i = 0; i < TM; i++) {
            int gr = row0 + rm + i;
            int hg = gr >> 11;
            int s  = gr & 2047;
            long long base = (long long)(hg * 512 + (s >> 2)) * FH_ + (s & 3) * 2048;
            #pragma unroll
            for (int j = 0; j < TN; j += 4) {
                long long idx = base + col0 + rn + j;
                *(float4*)(C + idx) = make_float4(acc[i][j], acc[i][j+1], acc[i][j+2], acc[i][j+3]);
            }
        }
    }
}

// ---------------- RoPE (in-place on Q and K, layout (b*s, 4096)) ----------------
__global__ void rope_kernel(float* __restrict__ Q, float* __restrict__ Kb,
                            const int* __restrict__ pos_ids)
{
    const int row = blockIdx.x;            // b*S + s
    const float p = (float)pos_ids[row];
    const long long base = (long long)row * HID_;
    // 2048 (head, d<64) pairs per row
    for (int t = threadIdx.x; t < NH_ * 64; t += blockDim.x) {
        int h = t >> 6;
        int d = t & 63;
        // inv_freq = 10000^(-d/64)
        float inv = exp2f(-(float)d * (13.287712379549449f / 64.0f));
        float ang = p * inv;
        float sn, cs;
        sincosf(ang, &sn, &cs);
        int c1 = h * D_ + d;
        int c2 = c1 + 64;
        float qx = Q[base + c1], qy = Q[base + c2];
        Q[base + c1] = qx * cs - qy * sn;
        Q[base + c2] = qy * cs + qx * sn;
        float kx = Kb[base + c1], ky = Kb[base + c2];
        Kb[base + c1] = kx * cs - ky * sn;
        Kb[base + c2] = ky * cs + kx * sn;
    }
}

// ---------------- row softmax over len-2048 rows ----------------
__global__ void __launch_bounds__(256) softmax_kernel(float* __restrict__ P)
{
    const long long row = blockIdx.x;
    float* r = P + row * (long long)S_;
    const int tid = threadIdx.x;
    float v[8];
    float m = -1e38f;
    #pragma unroll
    for (int i = 0; i < 8; i++) { v[i] = r[tid + i * 256]; m = fmaxf(m, v[i]); }
    __shared__ float red[256];
    red[tid] = m; __syncthreads();
    #pragma unroll
    for (int s = 128; s > 0; s >>= 1) {
        if (tid < s) red[tid] = fmaxf(red[tid], red[tid + s]);
        __syncthreads();
    }
    m = red[0];
    __syncthreads();
    float sum = 0.0f;
    #pragma unroll
    for (int i = 0; i < 8; i++) { v[i] = expf(v[i] - m); sum += v[i]; }
    red[tid] = sum; __syncthreads();
    #pragma unroll
    for (int s = 128; s > 0; s >>= 1) {
        if (tid < s) red[tid] += red[tid + s];
        __syncthreads();
    }
    float inv = 1.0f / red[0];
    #pragma unroll
    for (int i = 0; i < 8; i++) r[tid + i * 256] = v[i] * inv;
}

// ---------------- launcher ----------------
extern "C" void kernel_launch(void* const* d_in, const int* in_sizes, int n_in,
                              void* d_out, int out_size)
{
    const float* H   = (const float*)d_in[0];
    // d_in[1] = attention_mask (pure causal -> applied analytically)
    const int*   pos = (const int*)  d_in[2];
    const float* Wq  = (const float*)d_in[3];
    const float* WVT = (const float*)d_in[4];
    const float* U   = (const float*)d_in[5];
    const float* Wv  = (const float*)d_in[6];
    const float* Wo  = (const float*)d_in[7];
    float* out = (float*)d_out;

    float *Q, *K, *klat, *vlat, *P, *scr;
    cudaGetSymbolAddress((void**)&Q,    g_Q);
    cudaGetSymbolAddress((void**)&K,    g_K);
    cudaGetSymbolAddress((void**)&klat, g_klat);
    cudaGetSymbolAddress((void**)&vlat, g_vlat);
    cudaGetSymbolAddress((void**)&P,    g_P);
    cudaGetSymbolAddress((void**)&scr,  g_scr);

    const dim3 blk(256);
    const int BS = B_ * S_;            // 4096 rows

    // 1) Q = H @ Wq^T            (4096 x 4096, K=4096)
    sgemm<0, true><<<dim3(HID_/BN, BS/BM, 1), blk>>>(
        H, Wq, Q, BS, HID_, HID_, HID_, HID_, HID_,
        0, 0, 0, 0, 0, 0, 1, 1.0f);

    // 2) k_lat = H @ WVT^T       (4096 x 2048)
    sgemm<0, true><<<dim3((G_*RK_)/BN, BS/BM, 1), blk>>>(
        H, WVT, klat, BS, G_*RK_, HID_, HID_, HID_, G_*RK_,
        0, 0, 0, 0, 0, 0, 1, 1.0f);

    // 3) v_lat = H @ Wv^T        (4096 x 2048)
    sgemm<0, true><<<dim3((G_*FGD_)/BN, BS/BM, 1), blk>>>(
        H, Wv, vlat, BS, G_*FGD_, HID_, HID_, HID_, G_*FGD_,
        0, 0, 0, 0, 0, 0, 1, 1.0f);

    // 4) K reconstruction: per (b,g): (2048 x 512) = klat_g (2048x256) @ Ug^T
    sgemm<0, true><<<dim3(512/BN, S_/BM, B_*G_), blk>>>(
        klat, U, K, S_, 512, RK_, G_*RK_, G_*RK_, HID_,
        (long long)S_*(G_*RK_), RK_,            // A: b, g offsets
        0, RK_,                                 // B (U): g offset = g*256
        (long long)S_*HID_, 512,                // C: b, g*512
        G_, 1.0f);

    // 5) RoPE on Q and K
    rope_kernel<<<BS, 256>>>(Q, K, pos);

    // 6) scores: per (b,h): (2048 x 2048) = Q_h @ K_h^T / sqrt(D), causal mask
    sgemm<1, true><<<dim3(S_/BN, S_/BM, B_*NH_), blk>>>(
        Q, K, P, S_, S_, D_, HID_, HID_, S_,
        (long long)S_*HID_, D_,                 // A: b, h*128
        (long long)S_*HID_, D_,                 // B: b, h*128
        (long long)NH_*S_*S_, (long long)S_*S_, // C: b, h
        NH_, 0.08838834764831845f);

    // 7) softmax rows
    softmax_kernel<<<B_*NH_*S_, 256>>>(P);

    // 8) AV: per (b,g): (8192 x 256) = P_g (8192x2048) @ v_lat_g (2048x256), scramble store
    sgemm<2, false><<<dim3(FGD_/BN, (4*S_)/BM, B_*G_), blk>>>(
        P, vlat, scr, 4*S_, FGD_, S_, S_, G_*FGD_, 0,
        (long long)NH_*S_*S_, (long long)4*S_*S_,  // A: b, g (4 heads contiguous)
        (long long)S_*(G_*FGD_), FGD_,             // B: b, g*256
        (long long)S_*FH_, FGD_,                   // C: b, g*256
        G_, 1.0f);

    // 9) out = scr @ Wo^T        (4096 x 4096, K=8192)
    sgemm<0, true><<<dim3(HID_/BN, BS/BM, 1), blk>>>(
        scr, Wo, out, BS, HID_, FH_, FH_, FH_, HID_,
        0, 0, 0, 0, 0, 0, 1, 1.0f);
}

// round 3
// speedup vs baseline: 1.0021x; 1.0010x over previous
#include <cuda_runtime.h>
#include <math.h>

// ---------------- problem constants ----------------
static constexpr int B_   = 2;
static constexpr int S_   = 2048;
static constexpr int HID_ = 4096;
static constexpr int NH_  = 32;
static constexpr int D_   = 128;
static constexpr int G_   = 8;
static constexpr int RK_  = 256;
static constexpr int FGD_ = 256;   // fused group dim
static constexpr int FH_  = 8192;  // fused hidden dim

// ---------------- scratch (static device bss, no runtime alloc) ----------------
__device__ float g_Q   [(long long)B_ * S_ * HID_];        // 64 MB
__device__ float g_K   [(long long)B_ * S_ * HID_];        // 64 MB
__device__ float g_klat[(long long)B_ * S_ * (G_*RK_)];    // 32 MB
__device__ float g_vlat[(long long)B_ * S_ * (G_*FGD_)];   // 32 MB
__device__ float g_P   [(long long)B_ * NH_ * S_ * S_];    // 1 GiB
__device__ float g_scr [(long long)B_ * S_ * FH_];         // 128 MB

// ---------------- generic tiled SGEMM ----------------
// C[M,N] = A[M,K] * op(B)   op = B^T (TRB=true, B is [N,K]) or B (TRB=false, [K,N])
// MODE 0: plain store
// MODE 1: scores epilogue: val*scale, causal mask (col>row -> -1e30), tile early-out
// MODE 2: AV epilogue with PALU scramble store
//
// batch: z = zo*ziCount + zi ; pointer offsets zo*So + zi*Si per operand.
#define BM 128
#define BN 128
#define BK 16
#define TM 8
#define TN 8

template<int MODE, bool TRB>
__global__ void __launch_bounds__(256)
sgemm(const float* __restrict__ Ag, const float* __restrict__ Bg, float* __restrict__ Cg,
      int M, int N, int K, int lda, int ldb, int ldc,
      long long aSo, long long aSi, long long bSo, long long bSi,
      long long cSo, long long cSi, int ziCount, float scale)
{
    const int zo = blockIdx.z / ziCount;
    const int zi = blockIdx.z % ziCount;
    const float* A = Ag + zo * aSo + zi * aSi;
    const float* Bm = Bg + zo * bSo + zi * bSi;
    float* C = Cg + zo * cSo + zi * cSi;

    const int row0 = blockIdx.y * BM;
    const int col0 = blockIdx.x * BN;
    const int tid = threadIdx.x;
    const int rm = (tid >> 4) * TM;   // 0..120
    const int rn = (tid & 15) * TN;   // 0..120

    if (MODE == 1) {
        // fully-masked tile (all cols > all rows): write -1e30 and bail.
        if (col0 > row0 + BM - 1) {
            const float4 mv = make_float4(-1e30f, -1e30f, -1e30f, -1e30f);
            #pragma unroll
            for (int i = 0; i < TM; i++) {
                long long crow = (long long)(row0 + rm + i) * ldc + col0 + rn;
                *(float4*)(C + crow)     = mv;
                *(float4*)(C + crow + 4) = mv;
            }
            return;
        }
    }

    __shared__ float As[BK][BM];
    __shared__ float Bs[BK][BN];

    float acc[TM][TN];
    #pragma unroll
    for (int i = 0; i < TM; i++)
        #pragma unroll
        for (int j = 0; j < TN; j++) acc[i][j] = 0.0f;

    for (int k0 = 0; k0 < K; k0 += BK) {
        // A tile: BM x BK (store transposed into As[k][m])
        #pragma unroll
        for (int it = 0; it < 2; it++) {
            int idx = tid + it * 256;           // float4 index 0..511
            int ar = idx >> 2;                  // m 0..127
            int ac = (idx & 3) * 4;             // k 0,4,8,12
            float4 v = *(const float4*)(A + (long long)(row0 + ar) * lda + k0 + ac);
            As[ac + 0][ar] = v.x; As[ac + 1][ar] = v.y;
            As[ac + 2][ar] = v.z; As[ac + 3][ar] = v.w;
        }
        if (TRB) {
            // B tile: BN x BK from [N,K] row-major -> Bs[k][n]
            #pragma unroll
            for (int it = 0; it < 2; it++) {
                int idx = tid + it * 256;
                int br = idx >> 2;              // n 0..127
                int bc = (idx & 3) * 4;         // k
                float4 v = *(const float4*)(Bm + (long long)(col0 + br) * ldb + k0 + bc);
                Bs[bc + 0][br] = v.x; Bs[bc + 1][br] = v.y;
                Bs[bc + 2][br] = v.z; Bs[bc + 3][br] = v.w;
            }
        } else {
            // B tile: BK x BN from [K,N] row-major -> Bs[k][n] direct
            #pragma unroll
            for (int it = 0; it < 2; it++) {
                int idx = tid + it * 256;
                int br = idx >> 5;              // k 0..15
                int bc = (idx & 31) * 4;        // n
                float4 v = *(const float4*)(Bm + (long long)(k0 + br) * ldb + col0 + bc);
                *(float4*)&Bs[br][bc] = v;
            }
        }
        __syncthreads();

        #pragma unroll
        for (int kk = 0; kk < BK; kk++) {
            float a[TM], b[TN];
            #pragma unroll
            for (int i = 0; i < TM; i++) a[i] = As[kk][rm + i];
            #pragma unroll
            for (int j = 0; j < TN; j++) b[j] = Bs[kk][rn + j];
            #pragma unroll
            for (int i = 0; i < TM; i++)
                #pragma unroll
                for (int j = 0; j < TN; j++)
                    acc[i][j] = fmaf(a[i], b[j], acc[i][j]);
        }
        __syncthreads();
    }

    if (MODE == 0) {
        #pragma unroll
        for (int i = 0; i < TM; i++) {
            long long crow = (long long)(row0 + rm + i) * ldc + col0 + rn;
            *(float4*)(C + crow)     = make_float4(acc[i][0], acc[i][1], acc[i][2], acc[i][3]);
            *(float4*)(C + crow + 4) = make_float4(acc[i][4], acc[i][5], acc[i][6], acc[i][7]);
        }
    } else if (MODE == 1) {
        #pragma unroll
        for (int i = 0; i < TM; i++) {
            int gr = row0 + rm + i;
            long long crow = (long long)gr * ldc;
            #pragma unroll
            for (int j = 0; j < TN; j++) {
                int gc = col0 + rn + j;
                float v = acc[i][j] * scale;
                if (gc > gr) v = -1e30f;
                C[crow + gc] = v;
            }
        }
    } else { // MODE 2: PALU scramble store
        // row gr = hg*2048 + s ; col = f (0..255). C already offset by b,g.
        #pragma unroll
        for (int i = 0; i < TM; i++) {
            int gr = row0 + rm + i;
            int hg = gr >> 11;
            int s  = gr & 2047;
            long long base = (long long)(hg * 512 + (s >> 2)) * FH_ + (s & 3) * 2048;
            #pragma unroll
            for (int j = 0; j < TN; j += 4) {
                long long idx = base + col0 + rn + j;
                *(float4*)(C + idx) = make_float4(acc[i][j], acc[i][j+1], acc[i][j+2], acc[i][j+3]);
            }
        }
    }
}

// ---------------- RoPE (in-place on Q and K, layout (b*s, 4096)) ----------------
__global__ void rope_kernel(float* __restrict__ Q, float* __restrict__ Kb,
                            const int* __restrict__ pos_ids)
{
    const int row = blockIdx.x;            // b*S + s
    const float p = (float)pos_ids[row];
    const long long base = (long long)row * HID_;
    // 2048 (head, d<64) pairs per row
    for (int t = threadIdx.x; t < NH_ * 64; t += blockDim.x) {
        int h = t >> 6;
        int d = t & 63;
        // inv_freq = 10000^(-d/64)
        float inv = exp2f(-(float)d * (13.287712379549449f / 64.0f));
        float ang = p * inv;
        float sn, cs;
        sincosf(ang, &sn, &cs);
        int c1 = h * D_ + d;
        int c2 = c1 + 64;
        float qx = Q[base + c1], qy = Q[base + c2];
        Q[base + c1] = qx * cs - qy * sn;
        Q[base + c2] = qy * cs + qx * sn;
        float kx = Kb[base + c1], ky = Kb[base + c2];
        Kb[base + c1] = kx * cs - ky * sn;
        Kb[base + c2] = ky * cs + kx * sn;
    }
}

// ---------------- row softmax over len-2048 rows ----------------
__global__ void __launch_bounds__(256) softmax_kernel(float* __restrict__ P)
{
    const long long row = blockIdx.x;
    float* r = P + row * (long long)S_;
    const int tid = threadIdx.x;
    float v[8];
    float m = -1e38f;
    #pragma unroll
    for (int i = 0; i < 8; i++) { v[i] = r[tid + i * 256]; m = fmaxf(m, v[i]); }
    __shared__ float red[256];
    red[tid] = m; __syncthreads();
    #pragma unroll
    for (int s = 128; s > 0; s >>= 1) {
        if (tid < s) red[tid] = fmaxf(red[tid], red[tid + s]);
        __syncthreads();
    }
    m = red[0];
    __syncthreads();
    float sum = 0.0f;
    #pragma unroll
    for (int i = 0; i < 8; i++) { v[i] = expf(v[i] - m); sum += v[i]; }
    red[tid] = sum; __syncthreads();
    #pragma unroll
    for (int s = 128; s > 0; s >>= 1) {
        if (tid < s) red[tid] += red[tid + s];
        __syncthreads();
    }
    float inv = 1.0f / red[0];
    #pragma unroll
    for (int i = 0; i < 8; i++) r[tid + i * 256] = v[i] * inv;
}

// ---------------- launcher ----------------
extern "C" void kernel_launch(void* const* d_in, const int* in_sizes, int n_in,
                              void* d_out, int out_size)
{
    const float* H   = (const float*)d_in[0];
    // d_in[1] = attention_mask (pure causal -> applied analytically)
    const int*   pos = (const int*)  d_in[2];
    const float* Wq  = (const float*)d_in[3];
    const float* WVT = (const float*)d_in[4];
    const float* U   = (const float*)d_in[5];
    const float* Wv  = (const float*)d_in[6];
    const float* Wo  = (const float*)d_in[7];
    float* out = (float*)d_out;

    float *Q, *K, *klat, *vlat, *P, *scr;
    cudaGetSymbolAddress((void**)&Q,    g_Q);
    cudaGetSymbolAddress((void**)&K,    g_K);
    cudaGetSymbolAddress((void**)&klat, g_klat);
    cudaGetSymbolAddress((void**)&vlat, g_vlat);
    cudaGetSymbolAddress((void**)&P,    g_P);
    cudaGetSymbolAddress((void**)&scr,  g_scr);

    const dim3 blk(256);
    const int BS = B_ * S_;            // 4096 rows

    // 1) Q = H @ Wq^T            (4096 x 4096, K=4096)
    sgemm<0, true><<<dim3(HID_/BN, BS/BM, 1), blk>>>(
        H, Wq, Q, BS, HID_, HID_, HID_, HID_, HID_,
        0, 0, 0, 0, 0, 0, 1, 1.0f);

    // 2) k_lat = H @ WVT^T       (4096 x 2048)
    sgemm<0, true><<<dim3((G_*RK_)/BN, BS/BM, 1), blk>>>(
        H, WVT, klat, BS, G_*RK_, HID_, HID_, HID_, G_*RK_,
        0, 0, 0, 0, 0, 0, 1, 1.0f);

    // 3) v_lat = H @ Wv^T        (4096 x 2048)
    sgemm<0, true><<<dim3((G_*FGD_)/BN, BS/BM, 1), blk>>>(
        H, Wv, vlat, BS, G_*FGD_, HID_, HID_, HID_, G_*FGD_,
        0, 0, 0, 0, 0, 0, 1, 1.0f);

    // 4) K reconstruction: per (b,g): (2048 x 512) = klat_g (2048x256) @ Ug^T
    sgemm<0, true><<<dim3(512/BN, S_/BM, B_*G_), blk>>>(
        klat, U, K, S_, 512, RK_, G_*RK_, G_*RK_, HID_,
        (long long)S_*(G_*RK_), RK_,            // A: b, g offsets
        0, RK_,                                 // B (U): g offset = g*256
        (long long)S_*HID_, 512,                // C: b, g*512
        G_, 1.0f);

    // 5) RoPE on Q and K
    rope_kernel<<<BS, 256>>>(Q, K, pos);

    // 6) scores: per (b,h): (2048 x 2048) = Q_h @ K_h^T / sqrt(D), causal mask
    sgemm<1, true><<<dim3(S_/BN, S_/BM, B_*NH_), blk>>>(
        Q, K, P, S_, S_, D_, HID_, HID_, S_,
        (long long)S_*HID_, D_,                 // A: b, h*128
        (long long)S_*HID_, D_,                 // B: b, h*128
        (long long)NH_*S_*S_, (long long)S_*S_, // C: b, h
        NH_, 0.08838834764831845f);

    // 7) softmax rows
    softmax_kernel<<<B_*NH_*S_, 256>>>(P);

    // 8) AV: per (b,g): (8192 x 256) = P_g (8192x2048) @ v_lat_g (2048x256), scramble store
    sgemm<2, false><<<dim3(FGD_/BN, (4*S_)/BM, B_*G_), blk>>>(
        P, vlat, scr, 4*S_, FGD_, S_, S_, G_*FGD_, 0,
        (long long)NH_*S_*S_, (long long)4*S_*S_,  // A: b, g (4 heads contiguous)
        (long long)S_*(G_*FGD_), FGD_,             // B: b, g*256
        (long long)S_*FH_, FGD_,                   // C: b, g*256
        G_, 1.0f);

    // 9) out = scr @ Wo^T        (4096 x 4096, K=8192)
    sgemm<0, true><<<dim3(HID_/BN, BS/BM, 1), blk>>>(
        scr, Wo, out, BS, HID_, FH_, FH_, FH_, HID_,
        0, 0, 0, 0, 0, 0, 1, 1.0f);
}

// round 6
// speedup vs baseline: 2.7352x; 2.7295x over previous
#include <cuda_runtime.h>
#include <cuda_bf16.h>
#include <stdint.h>
#include <math.h>

typedef __nv_bfloat16 bf16;
typedef long long ll;
typedef unsigned int u32;
typedef unsigned long long u64;

static constexpr int B_   = 2;
static constexpr int S_   = 2048;
static constexpr int HID_ = 4096;
static constexpr int NH_  = 32;
static constexpr int G_   = 8;
static constexpr int RK_  = 256;
static constexpr int FGD_ = 256;
static constexpr int FH_  = 8192;

static constexpr ll N_H   = (ll)B_ * S_ * HID_;
static constexpr ll N_WQ  = (ll)HID_ * HID_;
static constexpr ll N_WVT = (ll)(G_*RK_) * HID_;
static constexpr ll N_WV  = (ll)(G_*FGD_) * HID_;
static constexpr ll N_U   = (ll)512 * (G_*RK_);
static constexpr ll N_WO  = (ll)HID_ * FH_;
static constexpr ll N_LAT = (ll)B_ * S_ * (G_*RK_);
static constexpr ll N_P   = (ll)B_ * NH_ * S_ * S_;
static constexpr ll N_SCR = (ll)B_ * S_ * FH_;

__device__ bf16 g_Hh[N_H],     g_Hl[N_H];
__device__ bf16 g_Wqh[N_WQ],   g_Wql[N_WQ];
__device__ bf16 g_WVTh[N_WVT], g_WVTl[N_WVT];
__device__ bf16 g_Wvh[N_WV],   g_Wvl[N_WV];
__device__ bf16 g_Uh[N_U],     g_Ul[N_U];
__device__ bf16 g_Woh[N_WO],   g_Wol[N_WO];
__device__ float g_Qf[N_H],    g_Kf[N_H];
__device__ bf16 g_Qh[N_H], g_Ql[N_H], g_Kh[N_H], g_Kl[N_H];
__device__ bf16 g_klath[N_LAT], g_klatl[N_LAT];
__device__ float g_vlatf[N_LAT];
__device__ bf16 g_vTh[N_LAT],  g_vTl[N_LAT];
__device__ float g_Pf[N_P];
__device__ bf16 g_Ph[N_P],     g_Pl[N_P];
__device__ bf16 g_scrh[N_SCR], g_scrl[N_SCR];

// ---------------- PTX helpers (base ISA only: cp.async / ldmatrix / mma.sync) ----------------
__device__ __forceinline__ u32 smem_u32(const void* p) {
    u32 a;
    asm("{ .reg .u64 t; cvta.to.shared.u64 t, %1; cvt.u32.u64 %0, t; }" : "=r"(a) : "l"(p));
    return a;
}
__device__ __forceinline__ void cp16(u32 dst, const void* src) {
    asm volatile("cp.async.cg.shared.global [%0], [%1], 16;" :: "r"(dst), "l"(src));
}
__device__ __forceinline__ void cp_commit() { asm volatile("cp.async.commit_group;" ::: "memory"); }
__device__ __forceinline__ void cp_wait1()  { asm volatile("cp.async.wait_group 1;" ::: "memory"); }
__device__ __forceinline__ void cp_wait0()  { asm volatile("cp.async.wait_group 0;" ::: "memory"); }
__device__ __forceinline__ void ldsm4(u32* r, u32 addr) {
    asm volatile("ldmatrix.sync.aligned.m8n8.x4.shared.b16 {%0,%1,%2,%3}, [%4];"
                 : "=r"(r[0]), "=r"(r[1]), "=r"(r[2]), "=r"(r[3]) : "r"(addr));
}
__device__ __forceinline__ void mma16816(float* d, const u32* a, const u32* b) {
    asm volatile("mma.sync.aligned.m16n8k16.row.col.f32.bf16.bf16.f32 "
                 "{%0,%1,%2,%3}, {%4,%5,%6,%7}, {%8,%9}, {%0,%1,%2,%3};"
                 : "+f"(d[0]), "+f"(d[1]), "+f"(d[2]), "+f"(d[3])
                 : "r"(a[0]), "r"(a[1]), "r"(a[2]), "r"(a[3]), "r"(b[0]), "r"(b[1]));
}
__device__ __forceinline__ u32 pack_hi(float v0, float v1) {
    __nv_bfloat162 p = __halves2bfloat162(__float2bfloat16(v0), __float2bfloat16(v1));
    return *(u32*)&p;
}
__device__ __forceinline__ u32 pack_lo(float v0, float v1) {
    bf16 h0 = __float2bfloat16(v0), h1 = __float2bfloat16(v1);
    __nv_bfloat162 p = __halves2bfloat162(__float2bfloat16(v0 - __bfloat162float(h0)),
                                          __float2bfloat16(v1 - __bfloat162float(h1)));
    return *(u32*)&p;
}

// ======================================================================================
// warp-MMA bf16x3 GEMM: C[M,N] = (Ah+Al)[M,K] @ (Bh+Bl)[N,K]^T
// CTA tile 128x128, BK=32, 8 warps (2x4), warp tile 64x32, cp.async double buffer.
// MODE 0: f32 store    MODE 1: scores (scale + causal mask; skip fully-masked tiles)
// MODE 2: AV (K truncation + PALU scramble, dual-bf16)    MODE 3: dual-bf16 plain store
// ======================================================================================
static constexpr int STAGE = 32768;     // Ah 8K | Al 8K | Bh 8K | Bl 8K
static constexpr int SMEM_DYN = 2 * STAGE;

template<int MODE>
__global__ void __launch_bounds__(256, 1)
wgemm(const bf16* __restrict__ Ah, const bf16* __restrict__ Al,
      const bf16* __restrict__ Bh, const bf16* __restrict__ Bl,
      void* C0v, void* C1v, int K, int lda, int ldb, int ldc,
      ll aSo, ll aSi, ll bSo, ll bSi, ll cSo, ll cSi, int ziCount, float scale)
{
    const int row0 = blockIdx.y * 128;
    const int col0 = blockIdx.x * 128;
    if (MODE == 1 && col0 > row0 + 127) return;

    const int zo = blockIdx.z / ziCount, zi = blockIdx.z % ziCount;
    const ll aOff = (ll)zo * aSo + (ll)zi * aSi + (ll)row0 * lda;
    const ll bOff = (ll)zo * bSo + (ll)zi * bSi + (ll)col0 * ldb;
    Ah += aOff; Al += aOff; Bh += bOff; Bl += bOff;
    const ll cOff = (ll)zo * cSo + (ll)zi * cSi;

    int Keff = K;
    if (MODE == 2) { int lim = (row0 & 2047) + 128; if (lim < Keff) Keff = lim; }
    const int nK = Keff >> 5;

    extern __shared__ char sm[];
    const u32 sb = smem_u32(sm);
    const int tid = threadIdx.x, wid = tid >> 5, lane = tid & 31;
    const int wm = wid >> 2, wn = wid & 3;

    float acc[4][4][4];
    #pragma unroll
    for (int a = 0; a < 4; a++)
        #pragma unroll
        for (int b = 0; b < 4; b++)
            #pragma unroll
            for (int c = 0; c < 4; c++) acc[a][b][c] = 0.0f;

    // --- stage loader: 128 rows x 32 bf16 per operand, 16B-chunk XOR swizzle ---
    const int lr = tid >> 2;            // 0..63 base row pair handled below
    auto load_stage = [&](int kt, int buf) {
        const u32 sbase = sb + buf * STAGE;
        const int k0 = kt << 5;
        #pragma unroll
        for (int i = 0; i < 2; i++) {
            int idx = tid + i * 256;    // 0..511
            int r = idx >> 2, c = idx & 3;
            u32 d = sbase + r * 64 + (((c ^ (r & 3)) & 3) << 4);
            ll go = (ll)r * lda + k0 + c * 8;
            ll gb = (ll)r * ldb + k0 + c * 8;
            cp16(d,         Ah + go);
            cp16(d + 8192,  Al + go);
            cp16(d + 16384, Bh + gb);
            cp16(d + 24576, Bl + gb);
        }
    };

    load_stage(0, 0);
    cp_commit();

    for (int kt = 0; kt < nK; kt++) {
        if (kt + 1 < nK) { load_stage(kt + 1, (kt + 1) & 1); cp_commit(); cp_wait1(); }
        else             { cp_wait0(); }
        __syncthreads();

        const u32 abase = sb + (kt & 1) * STAGE;
        #pragma unroll
        for (int kk = 0; kk < 2; kk++) {
            u32 aH[4][4], aL[4][4], bH[4][2], bL[4][2];
            #pragma unroll
            for (int mi = 0; mi < 4; mi++) {
                int row = wm * 64 + mi * 16 + ((lane >> 3) & 1) * 8 + (lane & 7);
                int kb4 = kk * 2 + ((lane >> 4) & 1);
                u32 ad = abase + row * 64 + (((kb4 ^ (row & 3)) & 3) << 4);
                ldsm4(aH[mi], ad);
                ldsm4(aL[mi], ad + 8192);
            }
            #pragma unroll
            for (int nj = 0; nj < 2; nj++) {
                int n = wn * 32 + nj * 16 + ((lane >> 4) & 1) * 8 + (lane & 7);
                int kb4 = kk * 2 + ((lane >> 3) & 1);
                u32 bd = abase + 16384 + n * 64 + (((kb4 ^ (n & 3)) & 3) << 4);
                u32 t[4];
                ldsm4(t, bd);
                bH[nj*2][0] = t[0]; bH[nj*2][1] = t[1];
                bH[nj*2+1][0] = t[2]; bH[nj*2+1][1] = t[3];
                ldsm4(t, bd + 8192);
                bL[nj*2][0] = t[0]; bL[nj*2][1] = t[1];
                bL[nj*2+1][0] = t[2]; bL[nj*2+1][1] = t[3];
            }
            #pragma unroll
            for (int mi = 0; mi < 4; mi++)
                #pragma unroll
                for (int ni = 0; ni < 4; ni++) {
                    mma16816(acc[mi][ni], aH[mi], bH[ni]);
                    mma16816(acc[mi][ni], aH[mi], bL[ni]);
                    mma16816(acc[mi][ni], aL[mi], bH[ni]);
                }
        }
        __syncthreads();
    }

    // ---- epilogue ----
    const int g = lane >> 2, tig = lane & 3;
    #pragma unroll
    for (int mi = 0; mi < 4; mi++) {
        #pragma unroll
        for (int ni = 0; ni < 4; ni++) {
            int r1 = row0 + wm * 64 + mi * 16 + g;
            int r2 = r1 + 8;
            int col = col0 + wn * 32 + ni * 8 + tig * 2;
            float* ac = acc[mi][ni];
            if (MODE == 0) {
                float* C = (float*)C0v + cOff;
                *(float2*)(C + (ll)r1 * ldc + col) = make_float2(ac[0], ac[1]);
                *(float2*)(C + (ll)r2 * ldc + col) = make_float2(ac[2], ac[3]);
            } else if (MODE == 1) {
                float* C = (float*)C0v + cOff;
                float2 v1, v2;
                v1.x = (col     > r1) ? -1e30f : ac[0] * scale;
                v1.y = (col + 1 > r1) ? -1e30f : ac[1] * scale;
                v2.x = (col     > r2) ? -1e30f : ac[2] * scale;
                v2.y = (col + 1 > r2) ? -1e30f : ac[3] * scale;
                *(float2*)(C + (ll)r1 * ldc + col) = v1;
                *(float2*)(C + (ll)r2 * ldc + col) = v2;
            } else {
                bf16* Ch = (bf16*)C0v;
                bf16* Cl = (bf16*)C1v;
                ll b1, b2;
                if (MODE == 3) {
                    b1 = cOff + (ll)r1 * ldc + col;
                    b2 = cOff + (ll)r2 * ldc + col;
                } else {
                    int hg1 = r1 >> 11, s1 = r1 & 2047;
                    int hg2 = r2 >> 11, s2 = r2 & 2047;
                    b1 = cOff + (ll)(hg1 * 512 + (s1 >> 2)) * FH_ + (ll)(s1 & 3) * 2048 + col;
                    b2 = cOff + (ll)(hg2 * 512 + (s2 >> 2)) * FH_ + (ll)(s2 & 3) * 2048 + col;
                }
                *(u32*)(Ch + b1) = pack_hi(ac[0], ac[1]);
                *(u32*)(Cl + b1) = pack_lo(ac[0], ac[1]);
                *(u32*)(Ch + b2) = pack_hi(ac[2], ac[3]);
                *(u32*)(Cl + b2) = pack_lo(ac[2], ac[3]);
            }
        }
    }
}

// ============ elementwise fp32 -> (hi,lo) bf16 split, vectorized x4 ============
__global__ void convert_split(const float* __restrict__ in, bf16* __restrict__ h,
                              bf16* __restrict__ l, ll n4)
{
    ll i = (ll)blockIdx.x * blockDim.x + threadIdx.x;
    const ll stride = (ll)gridDim.x * blockDim.x;
    for (; i < n4; i += stride) {
        float4 v = __ldg((const float4*)in + i);
        ((uint2*)h)[i] = make_uint2(pack_hi(v.x, v.y), pack_hi(v.z, v.w));
        ((uint2*)l)[i] = make_uint2(pack_lo(v.x, v.y), pack_lo(v.z, v.w));
    }
}

// ============ RoPE: fp32 Q/K -> rotated (hi,lo) bf16 ============
__global__ void rope_split(const float* __restrict__ Qf, const float* __restrict__ Kf,
                           const int* __restrict__ pos,
                           bf16* __restrict__ Qh, bf16* __restrict__ Ql,
                           bf16* __restrict__ Kh, bf16* __restrict__ Kl)
{
    const int row = blockIdx.x;
    const float p = (float)__ldg(pos + row);
    const ll base = (ll)row * HID_;
    for (int t = threadIdx.x; t < NH_ * 64; t += blockDim.x) {
        int h = t >> 6, d = t & 63;
        float inv = exp2f(-(float)d * (13.287712379549449f / 64.0f));
        float sn, cs;
        sincosf(p * inv, &sn, &cs);
        ll c1 = base + h * 128 + d, c2 = c1 + 64;
        float qx = Qf[c1], qy = Qf[c2];
        float q1 = qx * cs - qy * sn, q2 = qy * cs + qx * sn;
        bf16 a = __float2bfloat16(q1); Qh[c1] = a; Ql[c1] = __float2bfloat16(q1 - __bfloat162float(a));
        bf16 b = __float2bfloat16(q2); Qh[c2] = b; Ql[c2] = __float2bfloat16(q2 - __bfloat162float(b));
        float kx = Kf[c1], ky = Kf[c2];
        float k1 = kx * cs - ky * sn, k2 = ky * cs + kx * sn;
        bf16 c = __float2bfloat16(k1); Kh[c1] = c; Kl[c1] = __float2bfloat16(k1 - __bfloat162float(c));
        bf16 e = __float2bfloat16(k2); Kh[c2] = e; Kl[c2] = __float2bfloat16(k2 - __bfloat162float(e));
    }
}

// ============ transpose + split: vlat[b*2048+s][2048] -> vT[b*2048+n][s] (hi,lo) ============
__global__ void transpose_split(const float* __restrict__ V, bf16* __restrict__ Th,
                                bf16* __restrict__ Tl)
{
    __shared__ float t[32][33];
    const int b = blockIdx.z, s0 = blockIdx.x * 32, n0 = blockIdx.y * 32;
    const int x = threadIdx.x;
    for (int y = threadIdx.y; y < 32; y += 8)
        t[y][x] = __ldg(V + (ll)(b * 2048 + s0 + y) * 2048 + n0 + x);
    __syncthreads();
    for (int yo = threadIdx.y; yo < 32; yo += 8) {
        float v = t[x][yo];
        bf16 h = __float2bfloat16(v);
        ll idx = (ll)(b * 2048 + n0 + yo) * 2048 + s0 + x;
        Th[idx] = h;
        Tl[idx] = __float2bfloat16(v - __bfloat162float(h));
    }
}

// ============ causal-prefix softmax: fp32 logits -> (hi,lo) bf16 probs ============
__global__ void __launch_bounds__(256) softmax_split(const float* __restrict__ Pf,
                                                     bf16* __restrict__ Ph, bf16* __restrict__ Pl)
{
    const ll row = blockIdx.x;
    const int rl = (int)(row & 2047);
    const int nproc = ((rl >> 7) + 1) << 7;
    const float* src = Pf + row * 2048;
    const int tid = threadIdx.x;
    float v[8];
    float m = -1e38f;
    #pragma unroll
    for (int i = 0; i < 8; i++) {
        int c = tid + i * 256;
        v[i] = (c < nproc) ? src[c] : -1e38f;
        m = fmaxf(m, v[i]);
    }
    __shared__ float red[256];
    red[tid] = m; __syncthreads();
    #pragma unroll
    for (int s = 128; s > 0; s >>= 1) {
        if (tid < s) red[tid] = fmaxf(red[tid], red[tid + s]);
        __syncthreads();
    }
    m = red[0];
    __syncthreads();
    float sum = 0.0f;
    #pragma unroll
    for (int i = 0; i < 8; i++) { v[i] = expf(v[i] - m); sum += v[i]; }
    red[tid] = sum; __syncthreads();
    #pragma unroll
    for (int s = 128; s > 0; s >>= 1) {
        if (tid < s) red[tid] += red[tid + s];
        __syncthreads();
    }
    const float inv = 1.0f / red[0];
    #pragma unroll
    for (int i = 0; i < 8; i++) {
        int c = tid + i * 256;
        if (c < nproc) {
            float pr = v[i] * inv;
            bf16 h = __float2bfloat16(pr);
            Ph[row * 2048 + c] = h;
            Pl[row * 2048 + c] = __float2bfloat16(pr - __bfloat162float(h));
        }
    }
}

// ============ launcher ============
extern "C" void kernel_launch(void* const* d_in, const int* in_sizes, int n_in,
                              void* d_out, int out_size)
{
    const float* H   = (const float*)d_in[0];
    const int*   pos = (const int*)  d_in[2];
    const float* Wq  = (const float*)d_in[3];
    const float* WVT = (const float*)d_in[4];
    const float* U   = (const float*)d_in[5];
    const float* Wv  = (const float*)d_in[6];
    const float* Wo  = (const float*)d_in[7];
    float* out = (float*)d_out;

    cudaFuncSetAttribute(wgemm<0>, cudaFuncAttributeMaxDynamicSharedMemorySize, SMEM_DYN);
    cudaFuncSetAttribute(wgemm<1>, cudaFuncAttributeMaxDynamicSharedMemorySize, SMEM_DYN);
    cudaFuncSetAttribute(wgemm<2>, cudaFuncAttributeMaxDynamicSharedMemorySize, SMEM_DYN);
    cudaFuncSetAttribute(wgemm<3>, cudaFuncAttributeMaxDynamicSharedMemorySize, SMEM_DYN);

    bf16 *Hh, *Hl, *Wqh, *Wql, *WVTh, *WVTl, *Wvh, *Wvl, *Uh, *Ul, *Woh, *Wol;
    bf16 *Qh, *Ql, *Kh, *Kl, *klath, *klatl, *vTh, *vTl, *Ph, *Pl, *scrh, *scrl;
    float *Qf, *Kf, *vlatf, *Pf;
    cudaGetSymbolAddress((void**)&Hh, g_Hh);       cudaGetSymbolAddress((void**)&Hl, g_Hl);
    cudaGetSymbolAddress((void**)&Wqh, g_Wqh);     cudaGetSymbolAddress((void**)&Wql, g_Wql);
    cudaGetSymbolAddress((void**)&WVTh, g_WVTh);   cudaGetSymbolAddress((void**)&WVTl, g_WVTl);
    cudaGetSymbolAddress((void**)&Wvh, g_Wvh);     cudaGetSymbolAddress((void**)&Wvl, g_Wvl);
    cudaGetSymbolAddress((void**)&Uh, g_Uh);       cudaGetSymbolAddress((void**)&Ul, g_Ul);
    cudaGetSymbolAddress((void**)&Woh, g_Woh);     cudaGetSymbolAddress((void**)&Wol, g_Wol);
    cudaGetSymbolAddress((void**)&Qf, g_Qf);       cudaGetSymbolAddress((void**)&Kf, g_Kf);
    cudaGetSymbolAddress((void**)&Qh, g_Qh);       cudaGetSymbolAddress((void**)&Ql, g_Ql);
    cudaGetSymbolAddress((void**)&Kh, g_Kh);       cudaGetSymbolAddress((void**)&Kl, g_Kl);
    cudaGetSymbolAddress((void**)&klath, g_klath); cudaGetSymbolAddress((void**)&klatl, g_klatl);
    cudaGetSymbolAddress((void**)&vlatf, g_vlatf);
    cudaGetSymbolAddress((void**)&vTh, g_vTh);     cudaGetSymbolAddress((void**)&vTl, g_vTl);
    cudaGetSymbolAddress((void**)&Pf, g_Pf);
    cudaGetSymbolAddress((void**)&Ph, g_Ph);       cudaGetSymbolAddress((void**)&Pl, g_Pl);
    cudaGetSymbolAddress((void**)&scrh, g_scrh);   cudaGetSymbolAddress((void**)&scrl, g_scrl);

    // 0) fp32 -> bf16 hi/lo splits
    convert_split<<<4096, 256>>>(H,   Hh,   Hl,   N_H   / 4);
    convert_split<<<4096, 256>>>(Wq,  Wqh,  Wql,  N_WQ  / 4);
    convert_split<<<4096, 256>>>(WVT, WVTh, WVTl, N_WVT / 4);
    convert_split<<<4096, 256>>>(Wv,  Wvh,  Wvl,  N_WV  / 4);
    convert_split<<<1024, 256>>>(U,   Uh,   Ul,   N_U   / 4);
    convert_split<<<4096, 256>>>(Wo,  Woh,  Wol,  N_WO  / 4);

    // 1) Q = H @ Wq^T  (4096x4096, K=4096) -> fp32
    wgemm<0><<<dim3(32, 32, 1), 256, SMEM_DYN>>>(
        Hh, Hl, Wqh, Wql, Qf, nullptr, HID_, HID_, HID_, HID_,
        0, 0, 0, 0, 0, 0, 1, 1.0f);
    // 2) klat = H @ WVT^T (4096x2048) -> bf16 hi/lo
    wgemm<3><<<dim3(16, 32, 1), 256, SMEM_DYN>>>(
        Hh, Hl, WVTh, WVTl, klath, klatl, HID_, HID_, HID_, 2048,
        0, 0, 0, 0, 0, 0, 1, 1.0f);
    // 3) vlat = H @ Wv^T (4096x2048) -> fp32
    wgemm<0><<<dim3(16, 32, 1), 256, SMEM_DYN>>>(
        Hh, Hl, Wvh, Wvl, vlatf, nullptr, HID_, HID_, HID_, 2048,
        0, 0, 0, 0, 0, 0, 1, 1.0f);
    // 4) vT = per-batch transpose of vlat, split to hi/lo
    transpose_split<<<dim3(64, 64, B_), dim3(32, 8)>>>(vlatf, vTh, vTl);
    // 5) K recon: per (b,g): (2048 x 512) = klat_g @ Ug^T -> fp32
    wgemm<0><<<dim3(4, 16, 16), 256, SMEM_DYN>>>(
        klath, klatl, Uh, Ul, Kf, nullptr, RK_, 2048, 2048, HID_,
        (ll)S_ * 2048, RK_, 0, RK_, (ll)S_ * HID_, 512, G_, 1.0f);
    // 6) RoPE -> hi/lo Q, K
    rope_split<<<B_ * S_, 256>>>(Qf, Kf, pos, Qh, Ql, Kh, Kl);
    // 7) scores: per (b,h): (2048 x 2048, K=128), scale + causal -> fp32
    wgemm<1><<<dim3(16, 16, 64), 256, SMEM_DYN>>>(
        Qh, Ql, Kh, Kl, Pf, nullptr, 128, HID_, HID_, S_,
        (ll)S_ * HID_, 128, (ll)S_ * HID_, 128,
        (ll)NH_ * S_ * S_, (ll)S_ * S_, NH_, 0.08838834764831845f);
    // 8) softmax -> bf16 hi/lo probs (causal prefix only)
    softmax_split<<<B_ * NH_ * S_, 256>>>(Pf, Ph, Pl);
    // 9) AV: per (b,g): (8192 x 256, K truncated per row-tile) -> scrambled bf16 hi/lo
    wgemm<2><<<dim3(2, 64, 16), 256, SMEM_DYN>>>(
        Ph, Pl, vTh, vTl, scrh, scrl, S_, S_, S_, 0,
        (ll)NH_ * S_ * S_, (ll)4 * S_ * S_,
        (ll)2048 * 2048, (ll)FGD_ * S_,
        (ll)S_ * FH_, FGD_, G_, 1.0f);
    // 10) out = scr @ Wo^T (4096x4096, K=8192)
    wgemm<0><<<dim3(32, 32, 1), 256, SMEM_DYN>>>(
        scrh, scrl, Woh, Wol, out, nullptr, FH_, FH_, FH_, HID_,
        0, 0, 0, 0, 0, 0, 1, 1.0f);
}

// round 7
// speedup vs baseline: 2.8878x; 1.0558x over previous
#include <cuda_runtime.h>
#include <cuda_bf16.h>
#include <stdint.h>
#include <math.h>

typedef __nv_bfloat16 bf16;
typedef long long ll;
typedef unsigned int u32;
typedef unsigned long long u64;

static constexpr int B_   = 2;
static constexpr int S_   = 2048;
static constexpr int HID_ = 4096;
static constexpr int NH_  = 32;
static constexpr int G_   = 8;
static constexpr int RK_  = 256;
static constexpr int FGD_ = 256;
static constexpr int FH_  = 8192;

static constexpr ll N_H   = (ll)B_ * S_ * HID_;
static constexpr ll N_WQ  = (ll)HID_ * HID_;
static constexpr ll N_WVT = (ll)(G_*RK_) * HID_;
static constexpr ll N_WV  = (ll)(G_*FGD_) * HID_;
static constexpr ll N_U   = (ll)512 * (G_*RK_);
static constexpr ll N_WO  = (ll)HID_ * FH_;
static constexpr ll N_LAT = (ll)B_ * S_ * (G_*RK_);
static constexpr ll N_P   = (ll)B_ * NH_ * S_ * S_;
static constexpr ll N_SCR = (ll)B_ * S_ * FH_;

__device__ bf16 g_Hh[N_H],     g_Hl[N_H];
__device__ bf16 g_Wqh[N_WQ],   g_Wql[N_WQ];
__device__ bf16 g_WVTh[N_WVT], g_WVTl[N_WVT];
__device__ bf16 g_Wvh[N_WV],   g_Wvl[N_WV];
__device__ bf16 g_Uh[N_U],     g_Ul[N_U];
__device__ bf16 g_Woh[N_WO],   g_Wol[N_WO];
__device__ float g_Qf[N_H],    g_Kf[N_H];
__device__ bf16 g_Qh[N_H], g_Ql[N_H], g_Kh[N_H], g_Kl[N_H];
__device__ bf16 g_klath[N_LAT], g_klatl[N_LAT];
__device__ float g_vlatf[N_LAT];
__device__ bf16 g_vTh[N_LAT],  g_vTl[N_LAT];
__device__ float g_Pf[N_P];
__device__ bf16 g_Ph[N_P],     g_Pl[N_P];
__device__ bf16 g_scrh[N_SCR], g_scrl[N_SCR];

// ---------------- PTX helpers (base ISA only: cp.async / ldmatrix / mma.sync) ----------------
__device__ __forceinline__ u32 smem_u32(const void* p) {
    u32 a;
    asm("{ .reg .u64 t; cvta.to.shared.u64 t, %1; cvt.u32.u64 %0, t; }" : "=r"(a) : "l"(p));
    return a;
}
__device__ __forceinline__ void cp16(u32 dst, const void* src) {
    asm volatile("cp.async.cg.shared.global [%0], [%1], 16;" :: "r"(dst), "l"(src));
}
__device__ __forceinline__ void cp_commit() { asm volatile("cp.async.commit_group;" ::: "memory"); }
__device__ __forceinline__ void cp_wait2()  { asm volatile("cp.async.wait_group 2;" ::: "memory"); }
__device__ __forceinline__ void ldsm4(u32* r, u32 addr) {
    asm volatile("ldmatrix.sync.aligned.m8n8.x4.shared.b16 {%0,%1,%2,%3}, [%4];"
                 : "=r"(r[0]), "=r"(r[1]), "=r"(r[2]), "=r"(r[3]) : "r"(addr));
}
__device__ __forceinline__ void mma16816(float* d, const u32* a, const u32* b) {
    asm volatile("mma.sync.aligned.m16n8k16.row.col.f32.bf16.bf16.f32 "
                 "{%0,%1,%2,%3}, {%4,%5,%6,%7}, {%8,%9}, {%0,%1,%2,%3};"
                 : "+f"(d[0]), "+f"(d[1]), "+f"(d[2]), "+f"(d[3])
                 : "r"(a[0]), "r"(a[1]), "r"(a[2]), "r"(a[3]), "r"(b[0]), "r"(b[1]));
}
__device__ __forceinline__ u32 pack_hi(float v0, float v1) {
    __nv_bfloat162 p = __halves2bfloat162(__float2bfloat16(v0), __float2bfloat16(v1));
    return *(u32*)&p;
}
__device__ __forceinline__ u32 pack_lo(float v0, float v1) {
    bf16 h0 = __float2bfloat16(v0), h1 = __float2bfloat16(v1);
    __nv_bfloat162 p = __halves2bfloat162(__float2bfloat16(v0 - __bfloat162float(h0)),
                                          __float2bfloat16(v1 - __bfloat162float(h1)));
    return *(u32*)&p;
}

// ======================================================================================
// warp-MMA bf16x3 GEMM v2: C[M,N] = (Ah+Al)[M,K] @ (Bh+Bl)[N,K]^T
// CTA tile 128x256, BK=32, 8 warps (2x4), warp tile 64x64, 3-stage cp.async pipeline.
// MODE 0: f32 store    MODE 1: scores (scale + causal mask; skip fully-masked tiles)
// MODE 2: AV (K truncation + PALU scramble, dual-bf16)    MODE 3: dual-bf16 plain store
// ======================================================================================
// stage layout: Ah 8K | Al 8K | Bh 16K | Bl 16K  = 48K ; 3 stages = 144K
static constexpr int STAGE = 49152;
static constexpr int SMEM_DYN = 3 * STAGE;

template<int MODE>
__global__ void __launch_bounds__(256, 1)
wgemm(const bf16* __restrict__ Ah, const bf16* __restrict__ Al,
      const bf16* __restrict__ Bh, const bf16* __restrict__ Bl,
      void* C0v, void* C1v, int K, int lda, int ldb, int ldc,
      ll aSo, ll aSi, ll bSo, ll bSi, ll cSo, ll cSi, int ziCount, float scale)
{
    const int row0 = blockIdx.y * 128;
    const int col0 = blockIdx.x * 256;
    if (MODE == 1 && col0 > row0 + 127) return;

    const int zo = blockIdx.z / ziCount, zi = blockIdx.z % ziCount;
    const ll aOff = (ll)zo * aSo + (ll)zi * aSi + (ll)row0 * lda;
    const ll bOff = (ll)zo * bSo + (ll)zi * bSi + (ll)col0 * ldb;
    Ah += aOff; Al += aOff; Bh += bOff; Bl += bOff;
    const ll cOff = (ll)zo * cSo + (ll)zi * cSi;

    int Keff = K;
    if (MODE == 2) { int lim = (row0 & 2047) + 128; if (lim < Keff) Keff = lim; }
    const int nK = Keff >> 5;

    extern __shared__ char sm[];
    const u32 sb = smem_u32(sm);
    const int tid = threadIdx.x, wid = tid >> 5, lane = tid & 31;
    const int wm = wid >> 2, wn = wid & 3;

    float acc[4][8][4];
    #pragma unroll
    for (int a = 0; a < 4; a++)
        #pragma unroll
        for (int b = 0; b < 8; b++)
            #pragma unroll
            for (int c = 0; c < 4; c++) acc[a][b][c] = 0.0f;

    // --- stage loader: A 128 rows, B 256 rows, 32 bf16 (64B) per row, XOR-16B swizzle ---
    auto load_stage = [&](int kt) {
        const u32 sbase = sb + (kt % 3) * STAGE;
        const int k0 = kt << 5;
        #pragma unroll
        for (int i = 0; i < 12; i++) {
            int idx = tid + i * 256;        // 0..3071 16B-chunks
            if (idx < 1024) {               // A: hi then lo, 512 chunks each
                int sub = idx >> 9;
                int m = idx & 511;
                int r = m >> 2, c = m & 3;
                u32 d = sbase + sub * 8192 + r * 64 + (((c ^ (r & 3)) & 3) << 4);
                const bf16* src = sub ? Al : Ah;
                cp16(d, src + (ll)r * lda + k0 + c * 8);
            } else {                        // B: hi then lo, 1024 chunks each
                int j = idx - 1024;
                int sub = j >> 10;
                int m = j & 1023;
                int r = m >> 2, c = m & 3;
                u32 d = sbase + 16384 + sub * 16384 + r * 64 + (((c ^ (r & 3)) & 3) << 4);
                const bf16* src = sub ? Bl : Bh;
                cp16(d, src + (ll)r * ldb + k0 + c * 8);
            }
        }
    };

    // prologue: 2 stages (always 2 commit groups)
    load_stage(0);
    cp_commit();
    if (nK > 1) load_stage(1);
    cp_commit();

    for (int kt = 0; kt < nK; kt++) {
        if (kt + 2 < nK) load_stage(kt + 2);
        cp_commit();                        // always commit (may be empty) -> wait semantics stay exact
        cp_wait2();                         // stage kt complete
        __syncthreads();

        const u32 abase = sb + (kt % 3) * STAGE;
        #pragma unroll
        for (int kk = 0; kk < 2; kk++) {
            u32 aH[4][4], aL[4][4];
            #pragma unroll
            for (int mi = 0; mi < 4; mi++) {
                int row = wm * 64 + mi * 16 + ((lane >> 3) & 1) * 8 + (lane & 7);
                int kb4 = kk * 2 + ((lane >> 4) & 1);
                u32 ad = abase + row * 64 + (((kb4 ^ (row & 3)) & 3) << 4);
                ldsm4(aH[mi], ad);
                ldsm4(aL[mi], ad + 8192);
            }
            #pragma unroll
            for (int nj = 0; nj < 4; nj++) {
                int n = wn * 64 + nj * 16 + ((lane >> 4) & 1) * 8 + (lane & 7);
                int kb4 = kk * 2 + ((lane >> 3) & 1);
                u32 bd = abase + 16384 + n * 64 + (((kb4 ^ (n & 3)) & 3) << 4);
                u32 tH[4], tL[4];
                ldsm4(tH, bd);
                ldsm4(tL, bd + 16384);
                #pragma unroll
                for (int mi = 0; mi < 4; mi++) {
                    mma16816(acc[mi][nj*2],     aH[mi], tH);
                    mma16816(acc[mi][nj*2],     aH[mi], tL);
                    mma16816(acc[mi][nj*2],     aL[mi], tH);
                    mma16816(acc[mi][nj*2+1],   aH[mi], tH + 2);
                    mma16816(acc[mi][nj*2+1],   aH[mi], tL + 2);
                    mma16816(acc[mi][nj*2+1],   aL[mi], tH + 2);
                }
            }
        }
        __syncthreads();
    }

    // ---- epilogue ----
    const int g = lane >> 2, tig = lane & 3;
    #pragma unroll
    for (int mi = 0; mi < 4; mi++) {
        #pragma unroll
        for (int ni = 0; ni < 8; ni++) {
            int r1 = row0 + wm * 64 + mi * 16 + g;
            int r2 = r1 + 8;
            int col = col0 + wn * 64 + ni * 8 + tig * 2;
            float* ac = acc[mi][ni];
            if (MODE == 0) {
                float* C = (float*)C0v + cOff;
                *(float2*)(C + (ll)r1 * ldc + col) = make_float2(ac[0], ac[1]);
                *(float2*)(C + (ll)r2 * ldc + col) = make_float2(ac[2], ac[3]);
            } else if (MODE == 1) {
                float* C = (float*)C0v + cOff;
                float2 v1, v2;
                v1.x = (col     > r1) ? -1e30f : ac[0] * scale;
                v1.y = (col + 1 > r1) ? -1e30f : ac[1] * scale;
                v2.x = (col     > r2) ? -1e30f : ac[2] * scale;
                v2.y = (col + 1 > r2) ? -1e30f : ac[3] * scale;
                *(float2*)(C + (ll)r1 * ldc + col) = v1;
                *(float2*)(C + (ll)r2 * ldc + col) = v2;
            } else {
                bf16* Ch = (bf16*)C0v;
                bf16* Cl = (bf16*)C1v;
                ll b1, b2;
                if (MODE == 3) {
                    b1 = cOff + (ll)r1 * ldc + col;
                    b2 = cOff + (ll)r2 * ldc + col;
                } else {
                    int hg1 = r1 >> 11, s1 = r1 & 2047;
                    int hg2 = r2 >> 11, s2 = r2 & 2047;
                    b1 = cOff + (ll)(hg1 * 512 + (s1 >> 2)) * FH_ + (ll)(s1 & 3) * 2048 + col;
                    b2 = cOff + (ll)(hg2 * 512 + (s2 >> 2)) * FH_ + (ll)(s2 & 3) * 2048 + col;
                }
                *(u32*)(Ch + b1) = pack_hi(ac[0], ac[1]);
                *(u32*)(Cl + b1) = pack_lo(ac[0], ac[1]);
                *(u32*)(Ch + b2) = pack_hi(ac[2], ac[3]);
                *(u32*)(Cl + b2) = pack_lo(ac[2], ac[3]);
            }
        }
    }
}

// ============ elementwise fp32 -> (hi,lo) bf16 split, vectorized x4 ============
__global__ void convert_split(const float* __restrict__ in, bf16* __restrict__ h,
                              bf16* __restrict__ l, ll n4)
{
    ll i = (ll)blockIdx.x * blockDim.x + threadIdx.x;
    const ll stride = (ll)gridDim.x * blockDim.x;
    for (; i < n4; i += stride) {
        float4 v = __ldg((const float4*)in + i);
        ((uint2*)h)[i] = make_uint2(pack_hi(v.x, v.y), pack_hi(v.z, v.w));
        ((uint2*)l)[i] = make_uint2(pack_lo(v.x, v.y), pack_lo(v.z, v.w));
    }
}

// ============ RoPE: fp32 Q/K -> rotated (hi,lo) bf16 ============
__global__ void rope_split(const float* __restrict__ Qf, const float* __restrict__ Kf,
                           const int* __restrict__ pos,
                           bf16* __restrict__ Qh, bf16* __restrict__ Ql,
                           bf16* __restrict__ Kh, bf16* __restrict__ Kl)
{
    const int row = blockIdx.x;
    const float p = (float)__ldg(pos + row);
    const ll base = (ll)row * HID_;
    for (int t = threadIdx.x; t < NH_ * 64; t += blockDim.x) {
        int h = t >> 6, d = t & 63;
        float inv = exp2f(-(float)d * (13.287712379549449f / 64.0f));
        float sn, cs;
        sincosf(p * inv, &sn, &cs);
        ll c1 = base + h * 128 + d, c2 = c1 + 64;
        float qx = Qf[c1], qy = Qf[c2];
        float q1 = qx * cs - qy * sn, q2 = qy * cs + qx * sn;
        bf16 a = __float2bfloat16(q1); Qh[c1] = a; Ql[c1] = __float2bfloat16(q1 - __bfloat162float(a));
        bf16 b = __float2bfloat16(q2); Qh[c2] = b; Ql[c2] = __float2bfloat16(q2 - __bfloat162float(b));
        float kx = Kf[c1], ky = Kf[c2];
        float k1 = kx * cs - ky * sn, k2 = ky * cs + kx * sn;
        bf16 c = __float2bfloat16(k1); Kh[c1] = c; Kl[c1] = __float2bfloat16(k1 - __bfloat162float(c));
        bf16 e = __float2bfloat16(k2); Kh[c2] = e; Kl[c2] = __float2bfloat16(k2 - __bfloat162float(e));
    }
}

// ============ transpose + split: vlat[b*2048+s][2048] -> vT[b*2048+n][s] (hi,lo) ============
__global__ void transpose_split(const float* __restrict__ V, bf16* __restrict__ Th,
                                bf16* __restrict__ Tl)
{
    __shared__ float t[32][33];
    const int b = blockIdx.z, s0 = blockIdx.x * 32, n0 = blockIdx.y * 32;
    const int x = threadIdx.x;
    for (int y = threadIdx.y; y < 32; y += 8)
        t[y][x] = __ldg(V + (ll)(b * 2048 + s0 + y) * 2048 + n0 + x);
    __syncthreads();
    for (int yo = threadIdx.y; yo < 32; yo += 8) {
        float v = t[x][yo];
        bf16 h = __float2bfloat16(v);
        ll idx = (ll)(b * 2048 + n0 + yo) * 2048 + s0 + x;
        Th[idx] = h;
        Tl[idx] = __float2bfloat16(v - __bfloat162float(h));
    }
}

// ============ causal-prefix softmax: fp32 logits -> (hi,lo) bf16 probs ============
__global__ void __launch_bounds__(256) softmax_split(const float* __restrict__ Pf,
                                                     bf16* __restrict__ Ph, bf16* __restrict__ Pl)
{
    const ll row = blockIdx.x;
    const int rl = (int)(row & 2047);
    const int nproc = ((rl >> 7) + 1) << 7;
    const float* src = Pf + row * 2048;
    const int tid = threadIdx.x;
    float v[8];
    float m = -1e38f;
    #pragma unroll
    for (int i = 0; i < 8; i++) {
        int c = tid + i * 256;
        v[i] = (c < nproc) ? src[c] : -1e38f;
        m = fmaxf(m, v[i]);
    }
    __shared__ float red[256];
    red[tid] = m; __syncthreads();
    #pragma unroll
    for (int s = 128; s > 0; s >>= 1) {
        if (tid < s) red[tid] = fmaxf(red[tid], red[tid + s]);
        __syncthreads();
    }
    m = red[0];
    __syncthreads();
    float sum = 0.0f;
    #pragma unroll
    for (int i = 0; i < 8; i++) { v[i] = expf(v[i] - m); sum += v[i]; }
    red[tid] = sum; __syncthreads();
    #pragma unroll
    for (int s = 128; s > 0; s >>= 1) {
        if (tid < s) red[tid] += red[tid + s];
        __syncthreads();
    }
    const float inv = 1.0f / red[0];
    #pragma unroll
    for (int i = 0; i < 8; i++) {
        int c = tid + i * 256;
        if (c < nproc) {
            float pr = v[i] * inv;
            bf16 h = __float2bfloat16(pr);
            Ph[row * 2048 + c] = h;
            Pl[row * 2048 + c] = __float2bfloat16(pr - __bfloat162float(h));
        }
    }
}

// ============ launcher ============
extern "C" void kernel_launch(void* const* d_in, const int* in_sizes, int n_in,
                              void* d_out, int out_size)
{
    const float* H   = (const float*)d_in[0];
    const int*   pos = (const int*)  d_in[2];
    const float* Wq  = (const float*)d_in[3];
    const float* WVT = (const float*)d_in[4];
    const float* U   = (const float*)d_in[5];
    const float* Wv  = (const float*)d_in[6];
    const float* Wo  = (const float*)d_in[7];
    float* out = (float*)d_out;

    cudaFuncSetAttribute(wgemm<0>, cudaFuncAttributeMaxDynamicSharedMemorySize, SMEM_DYN);
    cudaFuncSetAttribute(wgemm<1>, cudaFuncAttributeMaxDynamicSharedMemorySize, SMEM_DYN);
    cudaFuncSetAttribute(wgemm<2>, cudaFuncAttributeMaxDynamicSharedMemorySize, SMEM_DYN);
    cudaFuncSetAttribute(wgemm<3>, cudaFuncAttributeMaxDynamicSharedMemorySize, SMEM_DYN);

    bf16 *Hh, *Hl, *Wqh, *Wql, *WVTh, *WVTl, *Wvh, *Wvl, *Uh, *Ul, *Woh, *Wol;
    bf16 *Qh, *Ql, *Kh, *Kl, *klath, *klatl, *vTh, *vTl, *Ph, *Pl, *scrh, *scrl;
    float *Qf, *Kf, *vlatf, *Pf;
    cudaGetSymbolAddress((void**)&Hh, g_Hh);       cudaGetSymbolAddress((void**)&Hl, g_Hl);
    cudaGetSymbolAddress((void**)&Wqh, g_Wqh);     cudaGetSymbolAddress((void**)&Wql, g_Wql);
    cudaGetSymbolAddress((void**)&WVTh, g_WVTh);   cudaGetSymbolAddress((void**)&WVTl, g_WVTl);
    cudaGetSymbolAddress((void**)&Wvh, g_Wvh);     cudaGetSymbolAddress((void**)&Wvl, g_Wvl);
    cudaGetSymbolAddress((void**)&Uh, g_Uh);       cudaGetSymbolAddress((void**)&Ul, g_Ul);
    cudaGetSymbolAddress((void**)&Woh, g_Woh);     cudaGetSymbolAddress((void**)&Wol, g_Wol);
    cudaGetSymbolAddress((void**)&Qf, g_Qf);       cudaGetSymbolAddress((void**)&Kf, g_Kf);
    cudaGetSymbolAddress((void**)&Qh, g_Qh);       cudaGetSymbolAddress((void**)&Ql, g_Ql);
    cudaGetSymbolAddress((void**)&Kh, g_Kh);       cudaGetSymbolAddress((void**)&Kl, g_Kl);
    cudaGetSymbolAddress((void**)&klath, g_klath); cudaGetSymbolAddress((void**)&klatl, g_klatl);
    cudaGetSymbolAddress((void**)&vlatf, g_vlatf);
    cudaGetSymbolAddress((void**)&vTh, g_vTh);     cudaGetSymbolAddress((void**)&vTl, g_vTl);
    cudaGetSymbolAddress((void**)&Pf, g_Pf);
    cudaGetSymbolAddress((void**)&Ph, g_Ph);       cudaGetSymbolAddress((void**)&Pl, g_Pl);
    cudaGetSymbolAddress((void**)&scrh, g_scrh);   cudaGetSymbolAddress((void**)&scrl, g_scrl);

    // 0) fp32 -> bf16 hi/lo splits
    convert_split<<<4096, 256>>>(H,   Hh,   Hl,   N_H   / 4);
    convert_split<<<4096, 256>>>(Wq,  Wqh,  Wql,  N_WQ  / 4);
    convert_split<<<4096, 256>>>(WVT, WVTh, WVTl, N_WVT / 4);
    convert_split<<<4096, 256>>>(Wv,  Wvh,  Wvl,  N_WV  / 4);
    convert_split<<<1024, 256>>>(U,   Uh,   Ul,   N_U   / 4);
    convert_split<<<4096, 256>>>(Wo,  Woh,  Wol,  N_WO  / 4);

    // 1) Q = H @ Wq^T  (4096x4096, K=4096) -> fp32
    wgemm<0><<<dim3(16, 32, 1), 256, SMEM_DYN>>>(
        Hh, Hl, Wqh, Wql, Qf, nullptr, HID_, HID_, HID_, HID_,
        0, 0, 0, 0, 0, 0, 1, 1.0f);
    // 2) klat = H @ WVT^T (4096x2048) -> bf16 hi/lo
    wgemm<3><<<dim3(8, 32, 1), 256, SMEM_DYN>>>(
        Hh, Hl, WVTh, WVTl, klath, klatl, HID_, HID_, HID_, 2048,
        0, 0, 0, 0, 0, 0, 1, 1.0f);
    // 3) vlat = H @ Wv^T (4096x2048) -> fp32
    wgemm<0><<<dim3(8, 32, 1), 256, SMEM_DYN>>>(
        Hh, Hl, Wvh, Wvl, vlatf, nullptr, HID_, HID_, HID_, 2048,
        0, 0, 0, 0, 0, 0, 1, 1.0f);
    // 4) vT = per-batch transpose of vlat, split to hi/lo
    transpose_split<<<dim3(64, 64, B_), dim3(32, 8)>>>(vlatf, vTh, vTl);
    // 5) K recon: per (b,g): (2048 x 512) = klat_g @ Ug^T -> fp32
    wgemm<0><<<dim3(2, 16, 16), 256, SMEM_DYN>>>(
        klath, klatl, Uh, Ul, Kf, nullptr, RK_, 2048, 2048, HID_,
        (ll)S_ * 2048, RK_, 0, RK_, (ll)S_ * HID_, 512, G_, 1.0f);
    // 6) RoPE -> hi/lo Q, K
    rope_split<<<B_ * S_, 256>>>(Qf, Kf, pos, Qh, Ql, Kh, Kl);
    // 7) scores: per (b,h): (2048 x 2048, K=128), scale + causal -> fp32
    wgemm<1><<<dim3(8, 16, 64), 256, SMEM_DYN>>>(
        Qh, Ql, Kh, Kl, Pf, nullptr, 128, HID_, HID_, S_,
        (ll)S_ * HID_, 128, (ll)S_ * HID_, 128,
        (ll)NH_ * S_ * S_, (ll)S_ * S_, NH_, 0.08838834764831845f);
    // 8) softmax -> bf16 hi/lo probs (causal prefix only)
    softmax_split<<<B_ * NH_ * S_, 256>>>(Pf, Ph, Pl);
    // 9) AV: per (b,g): (8192 x 256, K truncated per row-tile) -> scrambled bf16 hi/lo
    wgemm<2><<<dim3(1, 64, 16), 256, SMEM_DYN>>>(
        Ph, Pl, vTh, vTl, scrh, scrl, S_, S_, S_, 0,
        (ll)NH_ * S_ * S_, (ll)4 * S_ * S_,
        (ll)2048 * 2048, (ll)FGD_ * S_,
        (ll)S_ * FH_, FGD_, G_, 1.0f);
    // 10) out = scr @ Wo^T (4096x4096, K=8192)
    wgemm<0><<<dim3(16, 32, 1), 256, SMEM_DYN>>>(
        scrh, scrl, Woh, Wol, out, nullptr, FH_, FH_, FH_, HID_,
        0, 0, 0, 0, 0, 0, 1, 1.0f);
}

// round 8
// speedup vs baseline: 3.9604x; 1.3714x over previous
#include <cuda_runtime.h>
#include <cuda_fp16.h>
#include <stdint.h>
#include <math.h>

typedef long long ll;
typedef unsigned int u32;
typedef unsigned long long u64;

static constexpr int B_   = 2;
static constexpr int S_   = 2048;
static constexpr int HID_ = 4096;
static constexpr int NH_  = 32;
static constexpr int G_   = 8;
static constexpr int RK_  = 256;
static constexpr int FGD_ = 256;
static constexpr int FH_  = 8192;

static constexpr ll N_H   = (ll)B_ * S_ * HID_;
static constexpr ll N_WQ  = (ll)HID_ * HID_;
static constexpr ll N_WVT = (ll)(G_*RK_) * HID_;
static constexpr ll N_WV  = (ll)(G_*FGD_) * HID_;
static constexpr ll N_U   = (ll)512 * (G_*RK_);
static constexpr ll N_WO  = (ll)HID_ * FH_;
static constexpr ll N_LAT = (ll)B_ * S_ * (G_*RK_);
static constexpr ll N_P   = (ll)B_ * NH_ * S_ * S_;
static constexpr ll N_SCR = (ll)B_ * S_ * FH_;

// A-side operands: hi/lo fp16 split. B-side weights/values: single fp16.
__device__ __half g_Hh[N_H],     g_Hl[N_H];
__device__ __half g_Wq1[N_WQ];
__device__ __half g_WVT1[N_WVT];
__device__ __half g_Wv1[N_WV];
__device__ __half g_U1[N_U];
__device__ __half g_Wo1[N_WO];
__device__ float  g_Qf[N_H],    g_Kf[N_H];
__device__ __half g_Qh[N_H], g_Ql[N_H], g_Kh[N_H], g_Kl[N_H];
__device__ __half g_klath[N_LAT], g_klatl[N_LAT];
__device__ float  g_vlatf[N_LAT];
__device__ __half g_vT1[N_LAT];
__device__ float  g_Pf[N_P];
__device__ __half g_Ph[N_P],     g_Pl[N_P];
__device__ __half g_scrh[N_SCR], g_scrl[N_SCR];

// ---------------- PTX helpers (base ISA: cp.async / ldmatrix / mma.sync) ----------------
__device__ __forceinline__ u32 smem_u32(const void* p) {
    u32 a;
    asm("{ .reg .u64 t; cvta.to.shared.u64 t, %1; cvt.u32.u64 %0, t; }" : "=r"(a) : "l"(p));
    return a;
}
__device__ __forceinline__ void cp16(u32 dst, const void* src) {
    asm volatile("cp.async.cg.shared.global [%0], [%1], 16;" :: "r"(dst), "l"(src));
}
__device__ __forceinline__ void cp_commit() { asm volatile("cp.async.commit_group;" ::: "memory"); }
__device__ __forceinline__ void cp_wait2()  { asm volatile("cp.async.wait_group 2;" ::: "memory"); }
__device__ __forceinline__ void ldsm4(u32* r, u32 addr) {
    asm volatile("ldmatrix.sync.aligned.m8n8.x4.shared.b16 {%0,%1,%2,%3}, [%4];"
                 : "=r"(r[0]), "=r"(r[1]), "=r"(r[2]), "=r"(r[3]) : "r"(addr));
}
__device__ __forceinline__ void mma16816(float* d, const u32* a, const u32* b) {
    asm volatile("mma.sync.aligned.m16n8k16.row.col.f32.f16.f16.f32 "
                 "{%0,%1,%2,%3}, {%4,%5,%6,%7}, {%8,%9}, {%0,%1,%2,%3};"
                 : "+f"(d[0]), "+f"(d[1]), "+f"(d[2]), "+f"(d[3])
                 : "r"(a[0]), "r"(a[1]), "r"(a[2]), "r"(a[3]), "r"(b[0]), "r"(b[1]));
}
__device__ __forceinline__ u32 pack_hi(float v0, float v1) {
    __half2 p = __halves2half2(__float2half_rn(v0), __float2half_rn(v1));
    return *(u32*)&p;
}
__device__ __forceinline__ u32 pack_lo(float v0, float v1) {
    __half h0 = __float2half_rn(v0), h1 = __float2half_rn(v1);
    __half2 p = __halves2half2(__float2half_rn(v0 - __half2float(h0)),
                               __float2half_rn(v1 - __half2float(h1)));
    return *(u32*)&p;
}

// ======================================================================================
// warp-MMA fp16 split GEMM: C[M,N] = (Ah+Al)[M,K] @ op(B)^T
//   BSPLIT=false: B single fp16, 2 MMAs/k-step (AhB + AlB)
//   BSPLIT=true : B hi/lo fp16, 3 MMAs/k-step (AhBh + AhBl + AlBh)
// CTA tile 128x256, BK=32, 8 warps (2x4), warp tile 64x64, 3-stage cp.async pipeline.
// MODE 0: f32 store    MODE 1: scores (scale + causal mask; skip fully-masked tiles)
// MODE 2: AV (K truncation + PALU scramble, dual-fp16)    MODE 3: dual-fp16 plain store
// ======================================================================================
template<int MODE, bool BSPLIT>
__global__ void __launch_bounds__(256, 1)
wgemm(const __half* __restrict__ Ah, const __half* __restrict__ Al,
      const __half* __restrict__ Bh, const __half* __restrict__ Bl,
      void* C0v, void* C1v, int K, int lda, int ldb, int ldc,
      ll aSo, ll aSi, ll bSo, ll bSi, ll cSo, ll cSi, int ziCount, float scale)
{
    constexpr int STAGE = BSPLIT ? 49152 : 32768;   // A 16K + B 16K(+16K lo)
    const int row0 = blockIdx.y * 128;
    const int col0 = blockIdx.x * 256;
    if (MODE == 1 && col0 > row0 + 127) return;

    const int zo = blockIdx.z / ziCount, zi = blockIdx.z % ziCount;
    const ll aOff = (ll)zo * aSo + (ll)zi * aSi + (ll)row0 * lda;
    const ll bOff = (ll)zo * bSo + (ll)zi * bSi + (ll)col0 * ldb;
    Ah += aOff; Al += aOff; Bh += bOff;
    if (BSPLIT) Bl += bOff;
    const ll cOff = (ll)zo * cSo + (ll)zi * cSi;

    int Keff = K;
    if (MODE == 2) { int lim = (row0 & 2047) + 128; if (lim < Keff) Keff = lim; }
    const int nK = Keff >> 5;

    extern __shared__ char sm[];
    const u32 sb = smem_u32(sm);
    const int tid = threadIdx.x, wid = tid >> 5, lane = tid & 31;
    const int wm = wid >> 2, wn = wid & 3;

    float acc[4][8][4];
    #pragma unroll
    for (int a = 0; a < 4; a++)
        #pragma unroll
        for (int b = 0; b < 8; b++)
            #pragma unroll
            for (int c = 0; c < 4; c++) acc[a][b][c] = 0.0f;

    // --- stage loader: A 128 rows (hi+lo), B 256 rows, 32 fp16 (64B)/row, XOR-16B swizzle ---
    auto load_stage = [&](int kt) {
        const u32 sbase = sb + (kt % 3) * STAGE;
        const int k0 = kt << 5;
        constexpr int NCHUNK = BSPLIT ? 12 : 8;     // 3072 or 2048 16B chunks / 256 thr
        #pragma unroll
        for (int i = 0; i < NCHUNK; i++) {
            int idx = tid + i * 256;
            if (idx < 1024) {                       // A: hi 512, lo 512
                int sub = idx >> 9;
                int m = idx & 511;
                int r = m >> 2, c = m & 3;
                u32 d = sbase + sub * 8192 + r * 64 + (((c ^ (r & 3)) & 3) << 4);
                const __half* src = sub ? Al : Ah;
                cp16(d, src + (ll)r * lda + k0 + c * 8);
            } else {                                // B
                int j = idx - 1024;
                int sub = BSPLIT ? (j >> 10) : 0;
                int m = BSPLIT ? (j & 1023) : j;
                int r = m >> 2, c = m & 3;
                u32 d = sbase + 16384 + sub * 16384 + r * 64 + (((c ^ (r & 3)) & 3) << 4);
                const __half* src = (BSPLIT && sub) ? Bl : Bh;
                cp16(d, src + (ll)r * ldb + k0 + c * 8);
            }
        }
    };

    load_stage(0);
    cp_commit();
    if (nK > 1) load_stage(1);
    cp_commit();

    for (int kt = 0; kt < nK; kt++) {
        if (kt + 2 < nK) load_stage(kt + 2);
        cp_commit();
        cp_wait2();
        __syncthreads();

        const u32 abase = sb + (kt % 3) * STAGE;
        #pragma unroll
        for (int kk = 0; kk < 2; kk++) {
            u32 aH[4][4], aL[4][4];
            #pragma unroll
            for (int mi = 0; mi < 4; mi++) {
                int row = wm * 64 + mi * 16 + ((lane >> 3) & 1) * 8 + (lane & 7);
                int kb4 = kk * 2 + ((lane >> 4) & 1);
                u32 ad = abase + row * 64 + (((kb4 ^ (row & 3)) & 3) << 4);
                ldsm4(aH[mi], ad);
                ldsm4(aL[mi], ad + 8192);
            }
            #pragma unroll
            for (int nj = 0; nj < 4; nj++) {
                int n = wn * 64 + nj * 16 + ((lane >> 4) & 1) * 8 + (lane & 7);
                int kb4 = kk * 2 + ((lane >> 3) & 1);
                u32 bd = abase + 16384 + n * 64 + (((kb4 ^ (n & 3)) & 3) << 4);
                u32 tH[4];
                ldsm4(tH, bd);
                if (BSPLIT) {
                    u32 tL[4];
                    ldsm4(tL, bd + 16384);
                    #pragma unroll
                    for (int mi = 0; mi < 4; mi++) {
                        mma16816(acc[mi][nj*2],   aH[mi], tH);
                        mma16816(acc[mi][nj*2],   aH[mi], tL);
                        mma16816(acc[mi][nj*2],   aL[mi], tH);
                        mma16816(acc[mi][nj*2+1], aH[mi], tH + 2);
                        mma16816(acc[mi][nj*2+1], aH[mi], tL + 2);
                        mma16816(acc[mi][nj*2+1], aL[mi], tH + 2);
                    }
                } else {
                    #pragma unroll
                    for (int mi = 0; mi < 4; mi++) {
                        mma16816(acc[mi][nj*2],   aH[mi], tH);
                        mma16816(acc[mi][nj*2],   aL[mi], tH);
                        mma16816(acc[mi][nj*2+1], aH[mi], tH + 2);
                        mma16816(acc[mi][nj*2+1], aL[mi], tH + 2);
                    }
                }
            }
        }
        __syncthreads();
    }

    // ---- epilogue ----
    const int g = lane >> 2, tig = lane & 3;
    #pragma unroll
    for (int mi = 0; mi < 4; mi++) {
        #pragma unroll
        for (int ni = 0; ni < 8; ni++) {
            int r1 = row0 + wm * 64 + mi * 16 + g;
            int r2 = r1 + 8;
            int col = col0 + wn * 64 + ni * 8 + tig * 2;
            float* ac = acc[mi][ni];
            if (MODE == 0) {
                float* C = (float*)C0v + cOff;
                *(float2*)(C + (ll)r1 * ldc + col) = make_float2(ac[0], ac[1]);
                *(float2*)(C + (ll)r2 * ldc + col) = make_float2(ac[2], ac[3]);
            } else if (MODE == 1) {
                float* C = (float*)C0v + cOff;
                float2 v1, v2;
                v1.x = (col     > r1) ? -1e30f : ac[0] * scale;
                v1.y = (col + 1 > r1) ? -1e30f : ac[1] * scale;
                v2.x = (col     > r2) ? -1e30f : ac[2] * scale;
                v2.y = (col + 1 > r2) ? -1e30f : ac[3] * scale;
                *(float2*)(C + (ll)r1 * ldc + col) = v1;
                *(float2*)(C + (ll)r2 * ldc + col) = v2;
            } else {
                __half* Ch = (__half*)C0v;
                __half* Cl = (__half*)C1v;
                ll b1, b2;
                if (MODE == 3) {
                    b1 = cOff + (ll)r1 * ldc + col;
                    b2 = cOff + (ll)r2 * ldc + col;
                } else {
                    int hg1 = r1 >> 11, s1 = r1 & 2047;
                    int hg2 = r2 >> 11, s2 = r2 & 2047;
                    b1 = cOff + (ll)(hg1 * 512 + (s1 >> 2)) * FH_ + (ll)(s1 & 3) * 2048 + col;
                    b2 = cOff + (ll)(hg2 * 512 + (s2 >> 2)) * FH_ + (ll)(s2 & 3) * 2048 + col;
                }
                *(u32*)(Ch + b1) = pack_hi(ac[0], ac[1]);
                *(u32*)(Cl + b1) = pack_lo(ac[0], ac[1]);
                *(u32*)(Ch + b2) = pack_hi(ac[2], ac[3]);
                *(u32*)(Cl + b2) = pack_lo(ac[2], ac[3]);
            }
        }
    }
}

// ============ fp32 -> (hi,lo) fp16 split, vectorized x4 ============
__global__ void convert_split(const float* __restrict__ in, __half* __restrict__ h,
                              __half* __restrict__ l, ll n4)
{
    ll i = (ll)blockIdx.x * blockDim.x + threadIdx.x;
    const ll stride = (ll)gridDim.x * blockDim.x;
    for (; i < n4; i += stride) {
        float4 v = __ldg((const float4*)in + i);
        ((uint2*)h)[i] = make_uint2(pack_hi(v.x, v.y), pack_hi(v.z, v.w));
        ((uint2*)l)[i] = make_uint2(pack_lo(v.x, v.y), pack_lo(v.z, v.w));
    }
}

// ============ fp32 -> single fp16, vectorized x4 ============
__global__ void convert_single(const float* __restrict__ in, __half* __restrict__ h, ll n4)
{
    ll i = (ll)blockIdx.x * blockDim.x + threadIdx.x;
    const ll stride = (ll)gridDim.x * blockDim.x;
    for (; i < n4; i += stride) {
        float4 v = __ldg((const float4*)in + i);
        ((uint2*)h)[i] = make_uint2(pack_hi(v.x, v.y), pack_hi(v.z, v.w));
    }
}

// ============ RoPE: fp32 Q/K -> rotated (hi,lo) fp16 ============
__global__ void rope_split(const float* __restrict__ Qf, const float* __restrict__ Kf,
                           const int* __restrict__ pos,
                           __half* __restrict__ Qh, __half* __restrict__ Ql,
                           __half* __restrict__ Kh, __half* __restrict__ Kl)
{
    const int row = blockIdx.x;
    const float p = (float)__ldg(pos + row);
    const ll base = (ll)row * HID_;
    for (int t = threadIdx.x; t < NH_ * 64; t += blockDim.x) {
        int h = t >> 6, d = t & 63;
        float inv = exp2f(-(float)d * (13.287712379549449f / 64.0f));
        float sn, cs;
        sincosf(p * inv, &sn, &cs);
        ll c1 = base + h * 128 + d, c2 = c1 + 64;
        float qx = Qf[c1], qy = Qf[c2];
        float q1 = qx * cs - qy * sn, q2 = qy * cs + qx * sn;
        __half a = __float2half_rn(q1); Qh[c1] = a; Ql[c1] = __float2half_rn(q1 - __half2float(a));
        __half b = __float2half_rn(q2); Qh[c2] = b; Ql[c2] = __float2half_rn(q2 - __half2float(b));
        float kx = Kf[c1], ky = Kf[c2];
        float k1 = kx * cs - ky * sn, k2 = ky * cs + kx * sn;
        __half c = __float2half_rn(k1); Kh[c1] = c; Kl[c1] = __float2half_rn(k1 - __half2float(c));
        __half e = __float2half_rn(k2); Kh[c2] = e; Kl[c2] = __float2half_rn(k2 - __half2float(e));
    }
}

// ============ transpose: vlat[b*2048+s][2048] -> vT[b*2048+n][s] single fp16 ============
__global__ void transpose_single(const float* __restrict__ V, __half* __restrict__ Th)
{
    __shared__ float t[32][33];
    const int b = blockIdx.z, s0 = blockIdx.x * 32, n0 = blockIdx.y * 32;
    const int x = threadIdx.x;
    for (int y = threadIdx.y; y < 32; y += 8)
        t[y][x] = __ldg(V + (ll)(b * 2048 + s0 + y) * 2048 + n0 + x);
    __syncthreads();
    for (int yo = threadIdx.y; yo < 32; yo += 8) {
        ll idx = (ll)(b * 2048 + n0 + yo) * 2048 + s0 + x;
        Th[idx] = __float2half_rn(t[x][yo]);
    }
}

// ============ causal-prefix softmax: fp32 logits -> (hi,lo) fp16 probs ============
__global__ void __launch_bounds__(256) softmax_split(const float* __restrict__ Pf,
                                                     __half* __restrict__ Ph, __half* __restrict__ Pl)
{
    const ll row = blockIdx.x;
    const int rl = (int)(row & 2047);
    const int nproc = ((rl >> 7) + 1) << 7;
    const float* src = Pf + row * 2048;
    const int tid = threadIdx.x;
    float v[8];
    float m = -1e38f;
    #pragma unroll
    for (int i = 0; i < 8; i++) {
        int c = tid + i * 256;
        v[i] = (c < nproc) ? src[c] : -1e38f;
        m = fmaxf(m, v[i]);
    }
    __shared__ float red[256];
    red[tid] = m; __syncthreads();
    #pragma unroll
    for (int s = 128; s > 0; s >>= 1) {
        if (tid < s) red[tid] = fmaxf(red[tid], red[tid + s]);
        __syncthreads();
    }
    m = red[0];
    __syncthreads();
    float sum = 0.0f;
    #pragma unroll
    for (int i = 0; i < 8; i++) { v[i] = expf(v[i] - m); sum += v[i]; }
    red[tid] = sum; __syncthreads();
    #pragma unroll
    for (int s = 128; s > 0; s >>= 1) {
        if (tid < s) red[tid] += red[tid + s];
        __syncthreads();
    }
    const float inv = 1.0f / red[0];
    #pragma unroll
    for (int i = 0; i < 8; i++) {
        int c = tid + i * 256;
        if (c < nproc) {
            float pr = v[i] * inv;
            __half h = __float2half_rn(pr);
            Ph[row * 2048 + c] = h;
            Pl[row * 2048 + c] = __float2half_rn(pr - __half2float(h));
        }
    }
}

// ============ launcher ============
extern "C" void kernel_launch(void* const* d_in, const int* in_sizes, int n_in,
                              void* d_out, int out_size)
{
    const float* H   = (const float*)d_in[0];
    const int*   pos = (const int*)  d_in[2];
    const float* Wq  = (const float*)d_in[3];
    const float* WVT = (const float*)d_in[4];
    const float* U   = (const float*)d_in[5];
    const float* Wv  = (const float*)d_in[6];
    const float* Wo  = (const float*)d_in[7];
    float* out = (float*)d_out;

    const int SMEM2 = 3 * 32768;    // BSPLIT=false
    const int SMEM3 = 3 * 49152;    // BSPLIT=true
    cudaFuncSetAttribute((const void*)wgemm<0,false>, cudaFuncAttributeMaxDynamicSharedMemorySize, SMEM2);
    cudaFuncSetAttribute((const void*)wgemm<1,true>,  cudaFuncAttributeMaxDynamicSharedMemorySize, SMEM3);
    cudaFuncSetAttribute((const void*)wgemm<2,false>, cudaFuncAttributeMaxDynamicSharedMemorySize, SMEM2);
    cudaFuncSetAttribute((const void*)wgemm<3,false>, cudaFuncAttributeMaxDynamicSharedMemorySize, SMEM2);

    __half *Hh, *Hl, *Wq1, *WVT1, *Wv1, *U1, *Wo1;
    __half *Qh, *Ql, *Kh, *Kl, *klath, *klatl, *vT1, *Ph, *Pl, *scrh, *scrl;
    float *Qf, *Kf, *vlatf, *Pf;
    cudaGetSymbolAddress((void**)&Hh, g_Hh);       cudaGetSymbolAddress((void**)&Hl, g_Hl);
    cudaGetSymbolAddress((void**)&Wq1, g_Wq1);
    cudaGetSymbolAddress((void**)&WVT1, g_WVT1);
    cudaGetSymbolAddress((void**)&Wv1, g_Wv1);
    cudaGetSymbolAddress((void**)&U1, g_U1);
    cudaGetSymbolAddress((void**)&Wo1, g_Wo1);
    cudaGetSymbolAddress((void**)&Qf, g_Qf);       cudaGetSymbolAddress((void**)&Kf, g_Kf);
    cudaGetSymbolAddress((void**)&Qh, g_Qh);       cudaGetSymbolAddress((void**)&Ql, g_Ql);
    cudaGetSymbolAddress((void**)&Kh, g_Kh);       cudaGetSymbolAddress((void**)&Kl, g_Kl);
    cudaGetSymbolAddress((void**)&klath, g_klath); cudaGetSymbolAddress((void**)&klatl, g_klatl);
    cudaGetSymbolAddress((void**)&vlatf, g_vlatf);
    cudaGetSymbolAddress((void**)&vT1, g_vT1);
    cudaGetSymbolAddress((void**)&Pf, g_Pf);
    cudaGetSymbolAddress((void**)&Ph, g_Ph);       cudaGetSymbolAddress((void**)&Pl, g_Pl);
    cudaGetSymbolAddress((void**)&scrh, g_scrh);   cudaGetSymbolAddress((void**)&scrl, g_scrl);

    // launches 0-4: converts needed before Q-proj (ncu -s 5 -c 1 then captures the GEMM)
    convert_split <<<4096, 256>>>(H,   Hh,  Hl, N_H   / 4);   // 0
    convert_single<<<4096, 256>>>(Wq,  Wq1,     N_WQ  / 4);   // 1
    convert_single<<<4096, 256>>>(WVT, WVT1,    N_WVT / 4);   // 2
    convert_single<<<4096, 256>>>(Wv,  Wv1,     N_WV  / 4);   // 3
    convert_single<<<1024, 256>>>(U,   U1,      N_U   / 4);   // 4

    // 5: Q = H @ Wq^T (4096x4096, K=4096) -> fp32     [PROFILED LAUNCH]
    wgemm<0,false><<<dim3(16, 32, 1), 256, SMEM2>>>(
        Hh, Hl, Wq1, nullptr, Qf, nullptr, HID_, HID_, HID_, HID_,
        0, 0, 0, 0, 0, 0, 1, 1.0f);

    // 6: Wo convert (needed only for final GEMM)
    convert_single<<<4096, 256>>>(Wo, Wo1, N_WO / 4);

    // 7: klat = H @ WVT^T (4096x2048) -> fp16 hi/lo
    wgemm<3,false><<<dim3(8, 32, 1), 256, SMEM2>>>(
        Hh, Hl, WVT1, nullptr, klath, klatl, HID_, HID_, HID_, 2048,
        0, 0, 0, 0, 0, 0, 1, 1.0f);
    // 8: vlat = H @ Wv^T (4096x2048) -> fp32
    wgemm<0,false><<<dim3(8, 32, 1), 256, SMEM2>>>(
        Hh, Hl, Wv1, nullptr, vlatf, nullptr, HID_, HID_, HID_, 2048,
        0, 0, 0, 0, 0, 0, 1, 1.0f);
    // 9: vT = per-batch transpose of vlat -> single fp16
    transpose_single<<<dim3(64, 64, B_), dim3(32, 8)>>>(vlatf, vT1);
    // 10: K recon: per (b,g): (2048 x 512) = klat_g @ Ug^T -> fp32
    wgemm<0,false><<<dim3(2, 16, 16), 256, SMEM2>>>(
        klath, klatl, U1, nullptr, Kf, nullptr, RK_, 2048, 2048, HID_,
        (ll)S_ * 2048, RK_, 0, RK_, (ll)S_ * HID_, 512, G_, 1.0f);
    // 11: RoPE -> hi/lo fp16 Q, K
    rope_split<<<B_ * S_, 256>>>(Qf, Kf, pos, Qh, Ql, Kh, Kl);
    // 12: scores: per (b,h): (2048 x 2048, K=128), 3-term, scale + causal -> fp32
    wgemm<1,true><<<dim3(8, 16, 64), 256, SMEM3>>>(
        Qh, Ql, Kh, Kl, Pf, nullptr, 128, HID_, HID_, S_,
        (ll)S_ * HID_, 128, (ll)S_ * HID_, 128,
        (ll)NH_ * S_ * S_, (ll)S_ * S_, NH_, 0.08838834764831845f);
    // 13: softmax -> fp16 hi/lo probs (causal prefix only)
    softmax_split<<<B_ * NH_ * S_, 256>>>(Pf, Ph, Pl);
    // 14: AV: per (b,g): (8192 x 256, K truncated) -> scrambled fp16 hi/lo
    wgemm<2,false><<<dim3(1, 64, 16), 256, SMEM2>>>(
        Ph, Pl, vT1, nullptr, scrh, scrl, S_, S_, S_, 0,
        (ll)NH_ * S_ * S_, (ll)4 * S_ * S_,
        (ll)2048 * 2048, (ll)FGD_ * S_,
        (ll)S_ * FH_, FGD_, G_, 1.0f);
    // 15: out = scr @ Wo^T (4096x4096, K=8192)
    wgemm<0,false><<<dim3(16, 32, 1), 256, SMEM2>>>(
        scrh, scrl, Wo1, nullptr, out, nullptr, FH_, FH_, FH_, HID_,
        0, 0, 0, 0, 0, 0, 1, 1.0f);
}

// round 9
// speedup vs baseline: 3.9658x; 1.0014x over previous
#include <cuda_runtime.h>
#include <cuda_fp16.h>
#include <stdint.h>
#include <math.h>

typedef long long ll;
typedef unsigned int u32;
typedef unsigned long long u64;

static constexpr int B_   = 2;
static constexpr int S_   = 2048;
static constexpr int HID_ = 4096;
static constexpr int NH_  = 32;
static constexpr int G_   = 8;
static constexpr int RK_  = 256;
static constexpr int FGD_ = 256;
static constexpr int FH_  = 8192;

static constexpr ll N_H   = (ll)B_ * S_ * HID_;
static constexpr ll N_WQ  = (ll)HID_ * HID_;
static constexpr ll N_WVT = (ll)(G_*RK_) * HID_;
static constexpr ll N_WV  = (ll)(G_*FGD_) * HID_;
static constexpr ll N_U   = (ll)512 * (G_*RK_);
static constexpr ll N_WO  = (ll)HID_ * FH_;
static constexpr ll N_LAT = (ll)B_ * S_ * (G_*RK_);
static constexpr ll N_P   = (ll)B_ * NH_ * S_ * S_;
static constexpr ll N_SCR = (ll)B_ * S_ * FH_;

__device__ __half g_Hh[N_H],     g_Hl[N_H];
__device__ __half g_Wq1[N_WQ];
__device__ __half g_WVT1[N_WVT];
__device__ __half g_Wv1[N_WV];
__device__ __half g_U1[N_U];
__device__ __half g_Wo1[N_WO];
__device__ float  g_Qf[N_H],    g_Kf[N_H];
__device__ __half g_Qh[N_H], g_Ql[N_H], g_Kh[N_H], g_Kl[N_H];
__device__ __half g_klath[N_LAT], g_klatl[N_LAT];
__device__ float  g_vlatf[N_LAT];
__device__ __half g_vT1[N_LAT];
__device__ float  g_Pf[N_P];
__device__ __half g_Ph[N_P],     g_Pl[N_P];
__device__ __half g_scrh[N_SCR], g_scrl[N_SCR];

// ---------------- PTX helpers ----------------
__device__ __forceinline__ u32 smem_u32(const void* p) {
    u32 a;
    asm("{ .reg .u64 t; cvta.to.shared.u64 t, %1; cvt.u32.u64 %0, t; }" : "=r"(a) : "l"(p));
    return a;
}
__device__ __forceinline__ void cp16(u32 dst, const void* src) {
    asm volatile("cp.async.cg.shared.global [%0], [%1], 16;" :: "r"(dst), "l"(src));
}
__device__ __forceinline__ void cp_commit() { asm volatile("cp.async.commit_group;" ::: "memory"); }
template<int N>
__device__ __forceinline__ void cp_waitN() { asm volatile("cp.async.wait_group %0;" :: "n"(N) : "memory"); }
__device__ __forceinline__ void ldsm4(u32* r, u32 addr) {
    asm volatile("ldmatrix.sync.aligned.m8n8.x4.shared.b16 {%0,%1,%2,%3}, [%4];"
                 : "=r"(r[0]), "=r"(r[1]), "=r"(r[2]), "=r"(r[3]) : "r"(addr));
}
__device__ __forceinline__ void mma16816(float* d, const u32* a, const u32* b) {
    asm volatile("mma.sync.aligned.m16n8k16.row.col.f32.f16.f16.f32 "
                 "{%0,%1,%2,%3}, {%4,%5,%6,%7}, {%8,%9}, {%0,%1,%2,%3};"
                 : "+f"(d[0]), "+f"(d[1]), "+f"(d[2]), "+f"(d[3])
                 : "r"(a[0]), "r"(a[1]), "r"(a[2]), "r"(a[3]), "r"(b[0]), "r"(b[1]));
}
__device__ __forceinline__ u32 pack_hi(float v0, float v1) {
    __half2 p = __halves2half2(__float2half_rn(v0), __float2half_rn(v1));
    return *(u32*)&p;
}
__device__ __forceinline__ u32 pack_lo(float v0, float v1) {
    __half h0 = __float2half_rn(v0), h1 = __float2half_rn(v1);
    __half2 p = __halves2half2(__float2half_rn(v0 - __half2float(h0)),
                               __float2half_rn(v1 - __half2float(h1)));
    return *(u32*)&p;
}

// ======================================================================================
// warp-MMA fp16 split GEMM: C[M,N] = (Ah+Al)[M,K] @ op(B)^T
//   BSPLIT=false: B single fp16, 2 MMAs/k-step, 4-stage pipeline (stage 32K)
//   BSPLIT=true : B hi/lo fp16, 3 MMAs/k-step, 3-stage pipeline (stage 48K)
// CTA tile 128x256, BK=32, 8 warps (2x4), warp tile 64x64.
// MODE 0: f32 store  MODE 1: scores (scale+causal; skip masked tiles)
// MODE 2: AV (K truncation + PALU scramble, dual-fp16)  MODE 3: dual-fp16 plain store
// ======================================================================================
template<int MODE, bool BSPLIT>
__global__ void __launch_bounds__(256, 1)
wgemm(const __half* __restrict__ Ah, const __half* __restrict__ Al,
      const __half* __restrict__ Bh, const __half* __restrict__ Bl,
      void* C0v, void* C1v, int K, int lda, int ldb, int ldc,
      ll aSo, ll aSi, ll bSo, ll bSi, ll cSo, ll cSi, int ziCount, float scale)
{
    constexpr int STAGE  = BSPLIT ? 49152 : 32768;
    constexpr int NSTAGE = BSPLIT ? 3 : 4;
    const int row0 = blockIdx.y * 128;
    const int col0 = blockIdx.x * 256;
    if (MODE == 1 && col0 > row0 + 127) return;

    const int zo = blockIdx.z / ziCount, zi = blockIdx.z % ziCount;
    const ll aOff = (ll)zo * aSo + (ll)zi * aSi + (ll)row0 * lda;
    const ll bOff = (ll)zo * bSo + (ll)zi * bSi + (ll)col0 * ldb;
    Ah += aOff; Al += aOff; Bh += bOff;
    if (BSPLIT) Bl += bOff;
    const ll cOff = (ll)zo * cSo + (ll)zi * cSi;

    int Keff = K;
    if (MODE == 2) { int lim = (row0 & 2047) + 128; if (lim < Keff) Keff = lim; }
    const int nK = Keff >> 5;

    extern __shared__ char sm[];
    const u32 sb = smem_u32(sm);
    const int tid = threadIdx.x, wid = tid >> 5, lane = tid & 31;
    const int wm = wid >> 2, wn = wid & 3;

    float acc[4][8][4];
    #pragma unroll
    for (int a = 0; a < 4; a++)
        #pragma unroll
        for (int b = 0; b < 8; b++)
            #pragma unroll
            for (int c = 0; c < 4; c++) acc[a][b][c] = 0.0f;

    auto load_stage = [&](int kt) {
        const u32 sbase = sb + (kt % NSTAGE) * STAGE;
        const int k0 = kt << 5;
        constexpr int NCHUNK = BSPLIT ? 12 : 8;
        #pragma unroll
        for (int i = 0; i < NCHUNK; i++) {
            int idx = tid + i * 256;
            if (idx < 1024) {                       // A: hi 512, lo 512
                int sub = idx >> 9;
                int m = idx & 511;
                int r = m >> 2, c = m & 3;
                u32 d = sbase + sub * 8192 + r * 64 + (((c ^ (r & 3)) & 3) << 4);
                const __half* src = sub ? Al : Ah;
                cp16(d, src + (ll)r * lda + k0 + c * 8);
            } else {                                // B
                int j = idx - 1024;
                int sub = BSPLIT ? (j >> 10) : 0;
                int m = BSPLIT ? (j & 1023) : j;
                int r = m >> 2, c = m & 3;
                u32 d = sbase + 16384 + sub * 16384 + r * 64 + (((c ^ (r & 3)) & 3) << 4);
                const __half* src = (BSPLIT && sub) ? Bl : Bh;
                cp16(d, src + (ll)r * ldb + k0 + c * 8);
            }
        }
    };

    #pragma unroll
    for (int s = 0; s < NSTAGE - 1; s++) {
        if (s == 0 || s < nK) load_stage(s);
        cp_commit();
    }

    for (int kt = 0; kt < nK; kt++) {
        if (kt + NSTAGE - 1 < nK) load_stage(kt + NSTAGE - 1);
        cp_commit();
        cp_waitN<NSTAGE - 1>();
        __syncthreads();

        const u32 abase = sb + (kt % NSTAGE) * STAGE;
        #pragma unroll
        for (int kk = 0; kk < 2; kk++) {
            u32 aH[4][4], aL[4][4];
            #pragma unroll
            for (int mi = 0; mi < 4; mi++) {
                int row = wm * 64 + mi * 16 + ((lane >> 3) & 1) * 8 + (lane & 7);
                int kb4 = kk * 2 + ((lane >> 4) & 1);
                u32 ad = abase + row * 64 + (((kb4 ^ (row & 3)) & 3) << 4);
                ldsm4(aH[mi], ad);
                ldsm4(aL[mi], ad + 8192);
            }
            #pragma unroll
            for (int nj = 0; nj < 4; nj++) {
                int n = wn * 64 + nj * 16 + ((lane >> 4) & 1) * 8 + (lane & 7);
                int kb4 = kk * 2 + ((lane >> 3) & 1);
                u32 bd = abase + 16384 + n * 64 + (((kb4 ^ (n & 3)) & 3) << 4);
                u32 tH[4];
                ldsm4(tH, bd);
                if (BSPLIT) {
                    u32 tL[4];
                    ldsm4(tL, bd + 16384);
                    #pragma unroll
                    for (int mi = 0; mi < 4; mi++) {
                        mma16816(acc[mi][nj*2],   aH[mi], tH);
                        mma16816(acc[mi][nj*2],   aH[mi], tL);
                        mma16816(acc[mi][nj*2],   aL[mi], tH);
                        mma16816(acc[mi][nj*2+1], aH[mi], tH + 2);
                        mma16816(acc[mi][nj*2+1], aH[mi], tL + 2);
                        mma16816(acc[mi][nj*2+1], aL[mi], tH + 2);
                    }
                } else {
                    #pragma unroll
                    for (int mi = 0; mi < 4; mi++) {
                        mma16816(acc[mi][nj*2],   aH[mi], tH);
                        mma16816(acc[mi][nj*2],   aL[mi], tH);
                        mma16816(acc[mi][nj*2+1], aH[mi], tH + 2);
                        mma16816(acc[mi][nj*2+1], aL[mi], tH + 2);
                    }
                }
            }
        }
        __syncthreads();
    }

    // ---- epilogue ----
    const int g = lane >> 2, tig = lane & 3;
    #pragma unroll
    for (int mi = 0; mi < 4; mi++) {
        #pragma unroll
        for (int ni = 0; ni < 8; ni++) {
            int r1 = row0 + wm * 64 + mi * 16 + g;
            int r2 = r1 + 8;
            int col = col0 + wn * 64 + ni * 8 + tig * 2;
            float* ac = acc[mi][ni];
            if (MODE == 0) {
                float* C = (float*)C0v + cOff;
                *(float2*)(C + (ll)r1 * ldc + col) = make_float2(ac[0], ac[1]);
                *(float2*)(C + (ll)r2 * ldc + col) = make_float2(ac[2], ac[3]);
            } else if (MODE == 1) {
                float* C = (float*)C0v + cOff;
                float2 v1, v2;
                v1.x = (col     > r1) ? -1e30f : ac[0] * scale;
                v1.y = (col + 1 > r1) ? -1e30f : ac[1] * scale;
                v2.x = (col     > r2) ? -1e30f : ac[2] * scale;
                v2.y = (col + 1 > r2) ? -1e30f : ac[3] * scale;
                *(float2*)(C + (ll)r1 * ldc + col) = v1;
                *(float2*)(C + (ll)r2 * ldc + col) = v2;
            } else {
                __half* Ch = (__half*)C0v;
                __half* Cl = (__half*)C1v;
                ll b1, b2;
                if (MODE == 3) {
                    b1 = cOff + (ll)r1 * ldc + col;
                    b2 = cOff + (ll)r2 * ldc + col;
                } else {
                    int hg1 = r1 >> 11, s1 = r1 & 2047;
                    int hg2 = r2 >> 11, s2 = r2 & 2047;
                    b1 = cOff + (ll)(hg1 * 512 + (s1 >> 2)) * FH_ + (ll)(s1 & 3) * 2048 + col;
                    b2 = cOff + (ll)(hg2 * 512 + (s2 >> 2)) * FH_ + (ll)(s2 & 3) * 2048 + col;
                }
                *(u32*)(Ch + b1) = pack_hi(ac[0], ac[1]);
                *(u32*)(Cl + b1) = pack_lo(ac[0], ac[1]);
                *(u32*)(Ch + b2) = pack_hi(ac[2], ac[3]);
                *(u32*)(Cl + b2) = pack_lo(ac[2], ac[3]);
            }
        }
    }
}

// ============ mega-convert: all fp32 -> fp16 conversions in ONE launch ============
static constexpr ll C_H   = N_H   / 4;                 // H (split)
static constexpr ll C_WQ  = C_H   + N_WQ  / 4;
static constexpr ll C_WVT = C_WQ  + N_WVT / 4;
static constexpr ll C_WV  = C_WVT + N_WV  / 4;
static constexpr ll C_U   = C_WV  + N_U   / 4;
static constexpr ll C_WO  = C_U   + N_WO  / 4;

__global__ void convert_all(const float* __restrict__ H,  const float* __restrict__ Wq,
                            const float* __restrict__ WVT, const float* __restrict__ Wv,
                            const float* __restrict__ U,  const float* __restrict__ Wo,
                            __half* __restrict__ Hh, __half* __restrict__ Hl,
                            __half* __restrict__ Wq1, __half* __restrict__ WVT1,
                            __half* __restrict__ Wv1, __half* __restrict__ U1,
                            __half* __restrict__ Wo1)
{
    ll i = (ll)blockIdx.x * blockDim.x + threadIdx.x;
    const ll stride = (ll)gridDim.x * blockDim.x;
    for (; i < C_WO; i += stride) {
        const float* src; __half* dh; __half* dl = nullptr; ll j;
        if (i < C_H)        { src = H;   dh = Hh;   dl = Hl; j = i; }
        else if (i < C_WQ)  { src = Wq;  dh = Wq1;  j = i - C_H; }
        else if (i < C_WVT) { src = WVT; dh = WVT1; j = i - C_WQ; }
        else if (i < C_WV)  { src = Wv;  dh = Wv1;  j = i - C_WVT; }
        else if (i < C_U)   { src = U;   dh = U1;   j = i - C_WV; }
        else                { src = Wo;  dh = Wo1;  j = i - C_U; }
        float4 v = __ldg((const float4*)src + j);
        ((uint2*)dh)[j] = make_uint2(pack_hi(v.x, v.y), pack_hi(v.z, v.w));
        if (dl) ((uint2*)dl)[j] = make_uint2(pack_lo(v.x, v.y), pack_lo(v.z, v.w));
    }
}

// ============ RoPE: fp32 Q/K -> rotated (hi,lo) fp16 ============
__global__ void rope_split(const float* __restrict__ Qf, const float* __restrict__ Kf,
                           const int* __restrict__ pos,
                           __half* __restrict__ Qh, __half* __restrict__ Ql,
                           __half* __restrict__ Kh, __half* __restrict__ Kl)
{
    const int row = blockIdx.x;
    const float p = (float)__ldg(pos + row);
    const ll base = (ll)row * HID_;
    for (int t = threadIdx.x; t < NH_ * 64; t += blockDim.x) {
        int h = t >> 6, d = t & 63;
        float inv = exp2f(-(float)d * (13.287712379549449f / 64.0f));
        float sn, cs;
        sincosf(p * inv, &sn, &cs);
        ll c1 = base + h * 128 + d, c2 = c1 + 64;
        float qx = Qf[c1], qy = Qf[c2];
        float q1 = qx * cs - qy * sn, q2 = qy * cs + qx * sn;
        __half a = __float2half_rn(q1); Qh[c1] = a; Ql[c1] = __float2half_rn(q1 - __half2float(a));
        __half b = __float2half_rn(q2); Qh[c2] = b; Ql[c2] = __float2half_rn(q2 - __half2float(b));
        float kx = Kf[c1], ky = Kf[c2];
        float k1 = kx * cs - ky * sn, k2 = ky * cs + kx * sn;
        __half c = __float2half_rn(k1); Kh[c1] = c; Kl[c1] = __float2half_rn(k1 - __half2float(c));
        __half e = __float2half_rn(k2); Kh[c2] = e; Kl[c2] = __float2half_rn(k2 - __half2float(e));
    }
}

// ============ transpose: vlat[b*2048+s][2048] -> vT[b*2048+n][s] single fp16 ============
__global__ void transpose_single(const float* __restrict__ V, __half* __restrict__ Th)
{
    __shared__ float t[32][33];
    const int b = blockIdx.z, s0 = blockIdx.x * 32, n0 = blockIdx.y * 32;
    const int x = threadIdx.x;
    for (int y = threadIdx.y; y < 32; y += 8)
        t[y][x] = __ldg(V + (ll)(b * 2048 + s0 + y) * 2048 + n0 + x);
    __syncthreads();
    for (int yo = threadIdx.y; yo < 32; yo += 8) {
        ll idx = (ll)(b * 2048 + n0 + yo) * 2048 + s0 + x;
        Th[idx] = __float2half_rn(t[x][yo]);
    }
}

// ============ causal-prefix softmax: fp32 logits -> (hi,lo) fp16 probs ============
__global__ void __launch_bounds__(256) softmax_split(const float* __restrict__ Pf,
                                                     __half* __restrict__ Ph, __half* __restrict__ Pl)
{
    const ll row = blockIdx.x;
    const int rl = (int)(row & 2047);
    const int nproc = ((rl >> 7) + 1) << 7;
    const float* src = Pf + row * 2048;
    const int tid = threadIdx.x;
    float v[8];
    float m = -1e38f;
    #pragma unroll
    for (int i = 0; i < 8; i++) {
        int c = tid + i * 256;
        v[i] = (c < nproc) ? src[c] : -1e38f;
        m = fmaxf(m, v[i]);
    }
    __shared__ float red[256];
    red[tid] = m; __syncthreads();
    #pragma unroll
    for (int s = 128; s > 0; s >>= 1) {
        if (tid < s) red[tid] = fmaxf(red[tid], red[tid + s]);
        __syncthreads();
    }
    m = red[0];
    __syncthreads();
    float sum = 0.0f;
    #pragma unroll
    for (int i = 0; i < 8; i++) { v[i] = expf(v[i] - m); sum += v[i]; }
    red[tid] = sum; __syncthreads();
    #pragma unroll
    for (int s = 128; s > 0; s >>= 1) {
        if (tid < s) red[tid] += red[tid + s];
        __syncthreads();
    }
    const float inv = 1.0f / red[0];
    #pragma unroll
    for (int i = 0; i < 8; i++) {
        int c = tid + i * 256;
        if (c < nproc) {
            float pr = v[i] * inv;
            __half h = __float2half_rn(pr);
            Ph[row * 2048 + c] = h;
            Pl[row * 2048 + c] = __float2half_rn(pr - __half2float(h));
        }
    }
}

// ============ launcher ============
extern "C" void kernel_launch(void* const* d_in, const int* in_sizes, int n_in,
                              void* d_out, int out_size)
{
    const float* H   = (const float*)d_in[0];
    const int*   pos = (const int*)  d_in[2];
    const float* Wq  = (const float*)d_in[3];
    const float* WVT = (const float*)d_in[4];
    const float* U   = (const float*)d_in[5];
    const float* Wv  = (const float*)d_in[6];
    const float* Wo  = (const float*)d_in[7];
    float* out = (float*)d_out;

    const int SMEM2 = 4 * 32768;    // BSPLIT=false, 4 stages
    const int SMEM3 = 3 * 49152;    // BSPLIT=true,  3 stages
    cudaFuncSetAttribute((const void*)wgemm<0,false>, cudaFuncAttributeMaxDynamicSharedMemorySize, SMEM2);
    cudaFuncSetAttribute((const void*)wgemm<1,true>,  cudaFuncAttributeMaxDynamicSharedMemorySize, SMEM3);
    cudaFuncSetAttribute((const void*)wgemm<2,false>, cudaFuncAttributeMaxDynamicSharedMemorySize, SMEM2);
    cudaFuncSetAttribute((const void*)wgemm<3,false>, cudaFuncAttributeMaxDynamicSharedMemorySize, SMEM2);

    __half *Hh, *Hl, *Wq1, *WVT1, *Wv1, *U1, *Wo1;
    __half *Qh, *Ql, *Kh, *Kl, *klath, *klatl, *vT1, *Ph, *Pl, *scrh, *scrl;
    float *Qf, *Kf, *vlatf, *Pf;
    cudaGetSymbolAddress((void**)&Hh, g_Hh);       cudaGetSymbolAddress((void**)&Hl, g_Hl);
    cudaGetSymbolAddress((void**)&Wq1, g_Wq1);
    cudaGetSymbolAddress((void**)&WVT1, g_WVT1);
    cudaGetSymbolAddress((void**)&Wv1, g_Wv1);
    cudaGetSymbolAddress((void**)&U1, g_U1);
    cudaGetSymbolAddress((void**)&Wo1, g_Wo1);
    cudaGetSymbolAddress((void**)&Qf, g_Qf);       cudaGetSymbolAddress((void**)&Kf, g_Kf);
    cudaGetSymbolAddress((void**)&Qh, g_Qh);       cudaGetSymbolAddress((void**)&Ql, g_Ql);
    cudaGetSymbolAddress((void**)&Kh, g_Kh);       cudaGetSymbolAddress((void**)&Kl, g_Kl);
    cudaGetSymbolAddress((void**)&klath, g_klath); cudaGetSymbolAddress((void**)&klatl, g_klatl);
    cudaGetSymbolAddress((void**)&vlatf, g_vlatf);
    cudaGetSymbolAddress((void**)&vT1, g_vT1);
    cudaGetSymbolAddress((void**)&Pf, g_Pf);
    cudaGetSymbolAddress((void**)&Ph, g_Ph);       cudaGetSymbolAddress((void**)&Pl, g_Pl);
    cudaGetSymbolAddress((void**)&scrh, g_scrh);   cudaGetSymbolAddress((void**)&scrl, g_scrl);

    // our launch 0: ALL converts in one kernel
    convert_all<<<8192, 256>>>(H, Wq, WVT, Wv, U, Wo, Hh, Hl, Wq1, WVT1, Wv1, U1, Wo1);

    // our launch 1: klat = H @ WVT^T (4096x2048) -> fp16 hi/lo
    wgemm<3,false><<<dim3(8, 32, 1), 256, SMEM2>>>(
        Hh, Hl, WVT1, nullptr, klath, klatl, HID_, HID_, HID_, 2048,
        0, 0, 0, 0, 0, 0, 1, 1.0f);
    // our launch 2: vlat = H @ Wv^T (4096x2048) -> fp32
    wgemm<0,false><<<dim3(8, 32, 1), 256, SMEM2>>>(
        Hh, Hl, Wv1, nullptr, vlatf, nullptr, HID_, HID_, HID_, 2048,
        0, 0, 0, 0, 0, 0, 1, 1.0f);
    // our launch 3: vT transpose
    transpose_single<<<dim3(64, 64, B_), dim3(32, 8)>>>(vlatf, vT1);
    // our launch 4: Q = H @ Wq^T (4096x4096, K=4096) -> fp32   [target of ncu -s 5]
    wgemm<0,false><<<dim3(16, 32, 1), 256, SMEM2>>>(
        Hh, Hl, Wq1, nullptr, Qf, nullptr, HID_, HID_, HID_, HID_,
        0, 0, 0, 0, 0, 0, 1, 1.0f);
    // our launch 5: K recon per (b,g): (2048x512, K=256) -> fp32
    wgemm<0,false><<<dim3(2, 16, 16), 256, SMEM2>>>(
        klath, klatl, U1, nullptr, Kf, nullptr, RK_, 2048, 2048, HID_,
        (ll)S_ * 2048, RK_, 0, RK_, (ll)S_ * HID_, 512, G_, 1.0f);
    // our launch 6: RoPE -> hi/lo fp16 Q, K
    rope_split<<<B_ * S_, 256>>>(Qf, Kf, pos, Qh, Ql, Kh, Kl);
    // our launch 7: scores per (b,h): (2048x2048, K=128), 3-term, scale+causal -> fp32
    wgemm<1,true><<<dim3(8, 16, 64), 256, SMEM3>>>(
        Qh, Ql, Kh, Kl, Pf, nullptr, 128, HID_, HID_, S_,
        (ll)S_ * HID_, 128, (ll)S_ * HID_, 128,
        (ll)NH_ * S_ * S_, (ll)S_ * S_, NH_, 0.08838834764831845f);
    // our launch 8: softmax -> fp16 hi/lo probs (causal prefix only)
    softmax_split<<<B_ * NH_ * S_, 256>>>(Pf, Ph, Pl);
    // our launch 9: AV per (b,g): (8192x256, K truncated) -> scrambled fp16 hi/lo
    wgemm<2,false><<<dim3(1, 64, 16), 256, SMEM2>>>(
        Ph, Pl, vT1, nullptr, scrh, scrl, S_, S_, S_, 0,
        (ll)NH_ * S_ * S_, (ll)4 * S_ * S_,
        (ll)2048 * 2048, (ll)FGD_ * S_,
        (ll)S_ * FH_, FGD_, G_, 1.0f);
    // our launch 10: out = scr @ Wo^T (4096x4096, K=8192)
    wgemm<0,false><<<dim3(16, 32, 1), 256, SMEM2>>>(
        scrh, scrl, Wo1, nullptr, out, nullptr, FH_, FH_, FH_, HID_,
        0, 0, 0, 0, 0, 0, 1, 1.0f);
}

// round 10
// speedup vs baseline: 4.6445x; 1.1711x over previous
#include <cuda_runtime.h>
#include <cuda_fp16.h>
#include <stdint.h>
#include <math.h>

typedef long long ll;
typedef unsigned int u32;
typedef unsigned long long u64;

static constexpr int B_   = 2;
static constexpr int S_   = 2048;
static constexpr int HID_ = 4096;
static constexpr int NH_  = 32;
static constexpr int G_   = 8;
static constexpr int RK_  = 256;
static constexpr int FGD_ = 256;
static constexpr int FH_  = 8192;

static constexpr ll N_H   = (ll)B_ * S_ * HID_;
static constexpr ll N_WQ  = (ll)HID_ * HID_;
static constexpr ll N_WVT = (ll)(G_*RK_) * HID_;
static constexpr ll N_WV  = (ll)(G_*FGD_) * HID_;
static constexpr ll N_U   = (ll)512 * (G_*RK_);
static constexpr ll N_WO  = (ll)HID_ * FH_;
static constexpr ll N_LAT = (ll)B_ * S_ * (G_*RK_);
static constexpr ll N_P   = (ll)B_ * NH_ * S_ * S_;
static constexpr ll N_SCR = (ll)B_ * S_ * FH_;

__device__ __half g_Hh[N_H],     g_Hl[N_H];
__device__ __half g_Wq1[N_WQ];
__device__ __half g_WVT1[N_WVT];
__device__ __half g_Wv1[N_WV];
__device__ __half g_U1[N_U];
__device__ __half g_Wo1[N_WO];
__device__ float  g_Qf[N_H],    g_Kf[N_H];
__device__ __half g_Qh[N_H], g_Ql[N_H], g_Kh[N_H], g_Kl[N_H];
__device__ __half g_klath[N_LAT], g_klatl[N_LAT];
__device__ float  g_vlatf[N_LAT];
__device__ __half g_vT1[N_LAT];
__device__ float  g_Pf[N_P];
__device__ __half g_Ph[N_P],     g_Pl[N_P];
__device__ __half g_scrh[N_SCR];

// ---------------- PTX helpers ----------------
__device__ __forceinline__ u32 smem_u32(const void* p) {
    u32 a;
    asm("{ .reg .u64 t; cvta.to.shared.u64 t, %1; cvt.u32.u64 %0, t; }" : "=r"(a) : "l"(p));
    return a;
}
__device__ __forceinline__ void cp16(u32 dst, const void* src) {
    asm volatile("cp.async.cg.shared.global [%0], [%1], 16;" :: "r"(dst), "l"(src));
}
__device__ __forceinline__ void cp_commit() { asm volatile("cp.async.commit_group;" ::: "memory"); }
template<int N>
__device__ __forceinline__ void cp_waitN() { asm volatile("cp.async.wait_group %0;" :: "n"(N) : "memory"); }
__device__ __forceinline__ void ldsm4(u32* r, u32 addr) {
    asm volatile("ldmatrix.sync.aligned.m8n8.x4.shared.b16 {%0,%1,%2,%3}, [%4];"
                 : "=r"(r[0]), "=r"(r[1]), "=r"(r[2]), "=r"(r[3]) : "r"(addr));
}
__device__ __forceinline__ void mma16816(float* d, const u32* a, const u32* b) {
    asm volatile("mma.sync.aligned.m16n8k16.row.col.f32.f16.f16.f32 "
                 "{%0,%1,%2,%3}, {%4,%5,%6,%7}, {%8,%9}, {%0,%1,%2,%3};"
                 : "+f"(d[0]), "+f"(d[1]), "+f"(d[2]), "+f"(d[3])
                 : "r"(a[0]), "r"(a[1]), "r"(a[2]), "r"(a[3]), "r"(b[0]), "r"(b[1]));
}
__device__ __forceinline__ u32 pack_hi(float v0, float v1) {
    __half2 p = __halves2half2(__float2half_rn(v0), __float2half_rn(v1));
    return *(u32*)&p;
}
__device__ __forceinline__ u32 pack_lo(float v0, float v1) {
    __half h0 = __float2half_rn(v0), h1 = __float2half_rn(v1);
    __half2 p = __halves2half2(__float2half_rn(v0 - __half2float(h0)),
                               __float2half_rn(v1 - __half2float(h1)));
    return *(u32*)&p;
}

// ======================================================================================
// warp-MMA fp16 GEMM, 3 precision levels:
//   PREC=1: A single fp16,  1 MMA/k-step, stage 24K, 5-deep pipeline
//   PREC=2: A hi/lo fp16,   2 MMAs/k-step, stage 32K, 4-deep
//   PREC=3: A hi/lo + B hi/lo, 3 MMAs/k-step, stage 48K, 3-deep
// CTA tile 128x256, BK=32, 8 warps (2x4), warp tile 64x64.
// MODE 0: f32 store  MODE 1: scores (scale+causal; skip masked tiles)
// MODE 2: AV (K truncation + PALU scramble; lo plane only if C1v!=null)
// MODE 3: dual/single-fp16 plain store
// ======================================================================================
template<int MODE, int PREC>
__global__ void __launch_bounds__(256, 1)
wgemm(const __half* __restrict__ Ah, const __half* __restrict__ Al,
      const __half* __restrict__ Bh, const __half* __restrict__ Bl,
      void* C0v, void* C1v, int K, int lda, int ldb, int ldc,
      ll aSo, ll aSi, ll bSo, ll bSi, ll cSo, ll cSi, int ziCount, float scale)
{
    constexpr int STAGE  = (PREC == 3) ? 49152 : (PREC == 2 ? 32768 : 24576);
    constexpr int NSTAGE = (PREC == 3) ? 3 : (PREC == 2 ? 4 : 5);
    constexpr int BOFF   = (PREC >= 2) ? 16384 : 8192;
    const int row0 = blockIdx.y * 128;
    const int col0 = blockIdx.x * 256;
    if (MODE == 1 && col0 > row0 + 127) return;

    const int zo = blockIdx.z / ziCount, zi = blockIdx.z % ziCount;
    const ll aOff = (ll)zo * aSo + (ll)zi * aSi + (ll)row0 * lda;
    const ll bOff = (ll)zo * bSo + (ll)zi * bSi + (ll)col0 * ldb;
    Ah += aOff; Bh += bOff;
    if (PREC >= 2) Al += aOff;
    if (PREC == 3) Bl += bOff;
    const ll cOff = (ll)zo * cSo + (ll)zi * cSi;

    int Keff = K;
    if (MODE == 2) { int lim = (row0 & 2047) + 128; if (lim < Keff) Keff = lim; }
    const int nK = Keff >> 5;

    extern __shared__ char sm[];
    const u32 sb = smem_u32(sm);
    const int tid = threadIdx.x, wid = tid >> 5, lane = tid & 31;
    const int wm = wid >> 2, wn = wid & 3;

    float acc[4][8][4];
    #pragma unroll
    for (int a = 0; a < 4; a++)
        #pragma unroll
        for (int b = 0; b < 8; b++)
            #pragma unroll
            for (int c = 0; c < 4; c++) acc[a][b][c] = 0.0f;

    auto load_stage = [&](int kt) {
        const u32 sbase = sb + (kt % NSTAGE) * STAGE;
        const int k0 = kt << 5;
        constexpr int NCHUNK = (PREC == 3) ? 12 : (PREC == 2 ? 8 : 6);
        constexpr int NA = (PREC >= 2) ? 1024 : 512;   // A chunks
        #pragma unroll
        for (int i = 0; i < NCHUNK; i++) {
            int idx = tid + i * 256;
            if (idx < NA) {                        // A: hi (and lo if PREC>=2)
                int sub = (PREC >= 2) ? (idx >> 9) : 0;
                int m = (PREC >= 2) ? (idx & 511) : idx;
                int r = m >> 2, c = m & 3;
                u32 d = sbase + sub * 8192 + r * 64 + (((c ^ (r & 3)) & 3) << 4);
                const __half* src = sub ? Al : Ah;
                cp16(d, src + (ll)r * lda + k0 + c * 8);
            } else {                               // B
                int j = idx - NA;
                int sub = (PREC == 3) ? (j >> 10) : 0;
                int m = (PREC == 3) ? (j & 1023) : j;
                int r = m >> 2, c = m & 3;
                u32 d = sbase + BOFF + sub * 16384 + r * 64 + (((c ^ (r & 3)) & 3) << 4);
                const __half* src = (PREC == 3 && sub) ? Bl : Bh;
                cp16(d, src + (ll)r * ldb + k0 + c * 8);
            }
        }
    };

    #pragma unroll
    for (int s = 0; s < NSTAGE - 1; s++) {
        if (s == 0 || s < nK) load_stage(s);
        cp_commit();
    }

    for (int kt = 0; kt < nK; kt++) {
        if (kt + NSTAGE - 1 < nK) load_stage(kt + NSTAGE - 1);
        cp_commit();
        cp_waitN<NSTAGE - 1>();
        __syncthreads();

        const u32 abase = sb + (kt % NSTAGE) * STAGE;
        #pragma unroll
        for (int kk = 0; kk < 2; kk++) {
            u32 aH[4][4], aL[4][4];
            #pragma unroll
            for (int mi = 0; mi < 4; mi++) {
                int row = wm * 64 + mi * 16 + ((lane >> 3) & 1) * 8 + (lane & 7);
                int kb4 = kk * 2 + ((lane >> 4) & 1);
                u32 ad = abase + row * 64 + (((kb4 ^ (row & 3)) & 3) << 4);
                ldsm4(aH[mi], ad);
                if (PREC >= 2) ldsm4(aL[mi], ad + 8192);
            }
            #pragma unroll
            for (int nj = 0; nj < 4; nj++) {
                int n = wn * 64 + nj * 16 + ((lane >> 4) & 1) * 8 + (lane & 7);
                int kb4 = kk * 2 + ((lane >> 3) & 1);
                u32 bd = abase + BOFF + n * 64 + (((kb4 ^ (n & 3)) & 3) << 4);
                u32 tH[4];
                ldsm4(tH, bd);
                if (PREC == 3) {
                    u32 tL[4];
                    ldsm4(tL, bd + 16384);
                    #pragma unroll
                    for (int mi = 0; mi < 4; mi++) {
                        mma16816(acc[mi][nj*2],   aH[mi], tH);
                        mma16816(acc[mi][nj*2],   aH[mi], tL);
                        mma16816(acc[mi][nj*2],   aL[mi], tH);
                        mma16816(acc[mi][nj*2+1], aH[mi], tH + 2);
                        mma16816(acc[mi][nj*2+1], aH[mi], tL + 2);
                        mma16816(acc[mi][nj*2+1], aL[mi], tH + 2);
                    }
                } else if (PREC == 2) {
                    #pragma unroll
                    for (int mi = 0; mi < 4; mi++) {
                        mma16816(acc[mi][nj*2],   aH[mi], tH);
                        mma16816(acc[mi][nj*2],   aL[mi], tH);
                        mma16816(acc[mi][nj*2+1], aH[mi], tH + 2);
                        mma16816(acc[mi][nj*2+1], aL[mi], tH + 2);
                    }
                } else {
                    #pragma unroll
                    for (int mi = 0; mi < 4; mi++) {
                        mma16816(acc[mi][nj*2],   aH[mi], tH);
                        mma16816(acc[mi][nj*2+1], aH[mi], tH + 2);
                    }
                }
            }
        }
        __syncthreads();
    }

    // ---- epilogue ----
    const int g = lane >> 2, tig = lane & 3;
    #pragma unroll
    for (int mi = 0; mi < 4; mi++) {
        #pragma unroll
        for (int ni = 0; ni < 8; ni++) {
            int r1 = row0 + wm * 64 + mi * 16 + g;
            int r2 = r1 + 8;
            int col = col0 + wn * 64 + ni * 8 + tig * 2;
            float* ac = acc[mi][ni];
            if (MODE == 0) {
                float* C = (float*)C0v + cOff;
                *(float2*)(C + (ll)r1 * ldc + col) = make_float2(ac[0], ac[1]);
                *(float2*)(C + (ll)r2 * ldc + col) = make_float2(ac[2], ac[3]);
            } else if (MODE == 1) {
                float* C = (float*)C0v + cOff;
                float2 v1, v2;
                v1.x = (col     > r1) ? -1e30f : ac[0] * scale;
                v1.y = (col + 1 > r1) ? -1e30f : ac[1] * scale;
                v2.x = (col     > r2) ? -1e30f : ac[2] * scale;
                v2.y = (col + 1 > r2) ? -1e30f : ac[3] * scale;
                *(float2*)(C + (ll)r1 * ldc + col) = v1;
                *(float2*)(C + (ll)r2 * ldc + col) = v2;
            } else {
                __half* Ch = (__half*)C0v;
                __half* Cl = (__half*)C1v;
                ll b1, b2;
                if (MODE == 3) {
                    b1 = cOff + (ll)r1 * ldc + col;
                    b2 = cOff + (ll)r2 * ldc + col;
                } else {
                    int hg1 = r1 >> 11, s1 = r1 & 2047;
                    int hg2 = r2 >> 11, s2 = r2 & 2047;
                    b1 = cOff + (ll)(hg1 * 512 + (s1 >> 2)) * FH_ + (ll)(s1 & 3) * 2048 + col;
                    b2 = cOff + (ll)(hg2 * 512 + (s2 >> 2)) * FH_ + (ll)(s2 & 3) * 2048 + col;
                }
                *(u32*)(Ch + b1) = pack_hi(ac[0], ac[1]);
                *(u32*)(Ch + b2) = pack_hi(ac[2], ac[3]);
                if (Cl) {
                    *(u32*)(Cl + b1) = pack_lo(ac[0], ac[1]);
                    *(u32*)(Cl + b2) = pack_lo(ac[2], ac[3]);
                }
            }
        }
    }
}

// ============ mega-convert: all fp32 -> fp16 conversions in ONE launch ============
static constexpr ll C_H   = N_H   / 4;
static constexpr ll C_WQ  = C_H   + N_WQ  / 4;
static constexpr ll C_WVT = C_WQ  + N_WVT / 4;
static constexpr ll C_WV  = C_WVT + N_WV  / 4;
static constexpr ll C_U   = C_WV  + N_U   / 4;
static constexpr ll C_WO  = C_U   + N_WO  / 4;

__global__ void convert_all(const float* __restrict__ H,  const float* __restrict__ Wq,
                            const float* __restrict__ WVT, const float* __restrict__ Wv,
                            const float* __restrict__ U,  const float* __restrict__ Wo,
                            __half* __restrict__ Hh, __half* __restrict__ Hl,
                            __half* __restrict__ Wq1, __half* __restrict__ WVT1,
                            __half* __restrict__ Wv1, __half* __restrict__ U1,
                            __half* __restrict__ Wo1)
{
    ll i = (ll)blockIdx.x * blockDim.x + threadIdx.x;
    const ll stride = (ll)gridDim.x * blockDim.x;
    for (; i < C_WO; i += stride) {
        const float* src; __half* dh; __half* dl = nullptr; ll j;
        if (i < C_H)        { src = H;   dh = Hh;   dl = Hl; j = i; }
        else if (i < C_WQ)  { src = Wq;  dh = Wq1;  j = i - C_H; }
        else if (i < C_WVT) { src = WVT; dh = WVT1; j = i - C_WQ; }
        else if (i < C_WV)  { src = Wv;  dh = Wv1;  j = i - C_WVT; }
        else if (i < C_U)   { src = U;   dh = U1;   j = i - C_WV; }
        else                { src = Wo;  dh = Wo1;  j = i - C_U; }
        float4 v = __ldg((const float4*)src + j);
        ((uint2*)dh)[j] = make_uint2(pack_hi(v.x, v.y), pack_hi(v.z, v.w));
        if (dl) ((uint2*)dl)[j] = make_uint2(pack_lo(v.x, v.y), pack_lo(v.z, v.w));
    }
}

// ============ RoPE: fp32 Q/K -> rotated (hi,lo) fp16 ============
__global__ void rope_split(const float* __restrict__ Qf, const float* __restrict__ Kf,
                           const int* __restrict__ pos,
                           __half* __restrict__ Qh, __half* __restrict__ Ql,
                           __half* __restrict__ Kh, __half* __restrict__ Kl)
{
    const int row = blockIdx.x;
    const float p = (float)__ldg(pos + row);
    const ll base = (ll)row * HID_;
    for (int t = threadIdx.x; t < NH_ * 64; t += blockDim.x) {
        int h = t >> 6, d = t & 63;
        float inv = exp2f(-(float)d * (13.287712379549449f / 64.0f));
        float sn, cs;
        sincosf(p * inv, &sn, &cs);
        ll c1 = base + h * 128 + d, c2 = c1 + 64;
        float qx = Qf[c1], qy = Qf[c2];
        float q1 = qx * cs - qy * sn, q2 = qy * cs + qx * sn;
        __half a = __float2half_rn(q1); Qh[c1] = a; Ql[c1] = __float2half_rn(q1 - __half2float(a));
        __half b = __float2half_rn(q2); Qh[c2] = b; Ql[c2] = __float2half_rn(q2 - __half2float(b));
        float kx = Kf[c1], ky = Kf[c2];
        float k1 = kx * cs - ky * sn, k2 = ky * cs + kx * sn;
        __half c = __float2half_rn(k1); Kh[c1] = c; Kl[c1] = __float2half_rn(k1 - __half2float(c));
        __half e = __float2half_rn(k2); Kh[c2] = e; Kl[c2] = __float2half_rn(k2 - __half2float(e));
    }
}

// ============ transpose: vlat[b*2048+s][2048] -> vT[b*2048+n][s] single fp16 ============
__global__ void transpose_single(const float* __restrict__ V, __half* __restrict__ Th)
{
    __shared__ float t[32][33];
    const int b = blockIdx.z, s0 = blockIdx.x * 32, n0 = blockIdx.y * 32;
    const int x = threadIdx.x;
    for (int y = threadIdx.y; y < 32; y += 8)
        t[y][x] = __ldg(V + (ll)(b * 2048 + s0 + y) * 2048 + n0 + x);
    __syncthreads();
    for (int yo = threadIdx.y; yo < 32; yo += 8) {
        ll idx = (ll)(b * 2048 + n0 + yo) * 2048 + s0 + x;
        Th[idx] = __float2half_rn(t[x][yo]);
    }
}

// ============ causal-prefix softmax: fp32 logits -> (hi,lo) fp16 probs ============
__global__ void __launch_bounds__(256) softmax_split(const float* __restrict__ Pf,
                                                     __half* __restrict__ Ph, __half* __restrict__ Pl)
{
    const ll row = blockIdx.x;
    const int rl = (int)(row & 2047);
    const int nproc = ((rl >> 7) + 1) << 7;
    const float* src = Pf + row * 2048;
    const int tid = threadIdx.x;
    float v[8];
    float m = -1e38f;
    #pragma unroll
    for (int i = 0; i < 8; i++) {
        int c = tid + i * 256;
        v[i] = (c < nproc) ? src[c] : -1e38f;
        m = fmaxf(m, v[i]);
    }
    __shared__ float red[256];
    red[tid] = m; __syncthreads();
    #pragma unroll
    for (int s = 128; s > 0; s >>= 1) {
        if (tid < s) red[tid] = fmaxf(red[tid], red[tid + s]);
        __syncthreads();
    }
    m = red[0];
    __syncthreads();
    float sum = 0.0f;
    #pragma unroll
    for (int i = 0; i < 8; i++) { v[i] = expf(v[i] - m); sum += v[i]; }
    red[tid] = sum; __syncthreads();
    #pragma unroll
    for (int s = 128; s > 0; s >>= 1) {
        if (tid < s) red[tid] += red[tid + s];
        __syncthreads();
    }
    const float inv = 1.0f / red[0];
    #pragma unroll
    for (int i = 0; i < 8; i++) {
        int c = tid + i * 256;
        if (c < nproc) {
            float pr = v[i] * inv;
            __half h = __float2half_rn(pr);
            Ph[row * 2048 + c] = h;
            Pl[row * 2048 + c] = __float2half_rn(pr - __half2float(h));
        }
    }
}

// ============ launcher ============
extern "C" void kernel_launch(void* const* d_in, const int* in_sizes, int n_in,
                              void* d_out, int out_size)
{
    const float* H   = (const float*)d_in[0];
    const int*   pos = (const int*)  d_in[2];
    const float* Wq  = (const float*)d_in[3];
    const float* WVT = (const float*)d_in[4];
    const float* U   = (const float*)d_in[5];
    const float* Wv  = (const float*)d_in[6];
    const float* Wo  = (const float*)d_in[7];
    float* out = (float*)d_out;

    const int SMEM1 = 5 * 24576;    // PREC=1
    const int SMEM2 = 4 * 32768;    // PREC=2
    const int SMEM3 = 3 * 49152;    // PREC=3
    cudaFuncSetAttribute((const void*)wgemm<0,2>, cudaFuncAttributeMaxDynamicSharedMemorySize, SMEM2);
    cudaFuncSetAttribute((const void*)wgemm<0,1>, cudaFuncAttributeMaxDynamicSharedMemorySize, SMEM1);
    cudaFuncSetAttribute((const void*)wgemm<1,3>, cudaFuncAttributeMaxDynamicSharedMemorySize, SMEM3);
    cudaFuncSetAttribute((const void*)wgemm<2,2>, cudaFuncAttributeMaxDynamicSharedMemorySize, SMEM2);
    cudaFuncSetAttribute((const void*)wgemm<3,2>, cudaFuncAttributeMaxDynamicSharedMemorySize, SMEM2);

    __half *Hh, *Hl, *Wq1, *WVT1, *Wv1, *U1, *Wo1;
    __half *Qh, *Ql, *Kh, *Kl, *klath, *klatl, *vT1, *Ph, *Pl, *scrh;
    float *Qf, *Kf, *vlatf, *Pf;
    cudaGetSymbolAddress((void**)&Hh, g_Hh);       cudaGetSymbolAddress((void**)&Hl, g_Hl);
    cudaGetSymbolAddress((void**)&Wq1, g_Wq1);
    cudaGetSymbolAddress((void**)&WVT1, g_WVT1);
    cudaGetSymbolAddress((void**)&Wv1, g_Wv1);
    cudaGetSymbolAddress((void**)&U1, g_U1);
    cudaGetSymbolAddress((void**)&Wo1, g_Wo1);
    cudaGetSymbolAddress((void**)&Qf, g_Qf);       cudaGetSymbolAddress((void**)&Kf, g_Kf);
    cudaGetSymbolAddress((void**)&Qh, g_Qh);       cudaGetSymbolAddress((void**)&Ql, g_Ql);
    cudaGetSymbolAddress((void**)&Kh, g_Kh);       cudaGetSymbolAddress((void**)&Kl, g_Kl);
    cudaGetSymbolAddress((void**)&klath, g_klath); cudaGetSymbolAddress((void**)&klatl, g_klatl);
    cudaGetSymbolAddress((void**)&vlatf, g_vlatf);
    cudaGetSymbolAddress((void**)&vT1, g_vT1);
    cudaGetSymbolAddress((void**)&Pf, g_Pf);
    cudaGetSymbolAddress((void**)&Ph, g_Ph);       cudaGetSymbolAddress((void**)&Pl, g_Pl);
    cudaGetSymbolAddress((void**)&scrh, g_scrh);

    // our launch 0: ALL converts in one kernel
    convert_all<<<8192, 256>>>(H, Wq, WVT, Wv, U, Wo, Hh, Hl, Wq1, WVT1, Wv1, U1, Wo1);

    // our launch 1: klat = H @ WVT^T (4096x2048) -> fp16 hi/lo
    wgemm<3,2><<<dim3(8, 32, 1), 256, SMEM2>>>(
        Hh, Hl, WVT1, nullptr, klath, klatl, HID_, HID_, HID_, 2048,
        0, 0, 0, 0, 0, 0, 1, 1.0f);
    // our launch 2: vlat = H @ Wv^T (4096x2048) -> fp32
    wgemm<0,2><<<dim3(8, 32, 1), 256, SMEM2>>>(
        Hh, Hl, Wv1, nullptr, vlatf, nullptr, HID_, HID_, HID_, 2048,
        0, 0, 0, 0, 0, 0, 1, 1.0f);
    // our launch 3: Q = H @ Wq^T (4096x4096, K=4096) -> fp32   [ncu target if prepend=2]
    wgemm<0,2><<<dim3(16, 32, 1), 256, SMEM2>>>(
        Hh, Hl, Wq1, nullptr, Qf, nullptr, HID_, HID_, HID_, HID_,
        0, 0, 0, 0, 0, 0, 1, 1.0f);
    // our launch 4: K recon per (b,g): (2048x512, K=256) -> fp32  [ncu target if prepend=1]
    wgemm<0,2><<<dim3(2, 16, 16), 256, SMEM2>>>(
        klath, klatl, U1, nullptr, Kf, nullptr, RK_, 2048, 2048, HID_,
        (ll)S_ * 2048, RK_, 0, RK_, (ll)S_ * HID_, 512, G_, 1.0f);
    // our launch 5: vT transpose
    transpose_single<<<dim3(64, 64, B_), dim3(32, 8)>>>(vlatf, vT1);
    // our launch 6: RoPE -> hi/lo fp16 Q, K
    rope_split<<<B_ * S_, 256>>>(Qf, Kf, pos, Qh, Ql, Kh, Kl);
    // our launch 7: scores per (b,h): (2048x2048, K=128), 3-term, scale+causal -> fp32
    wgemm<1,3><<<dim3(8, 16, 64), 256, SMEM3>>>(
        Qh, Ql, Kh, Kl, Pf, nullptr, 128, HID_, HID_, S_,
        (ll)S_ * HID_, 128, (ll)S_ * HID_, 128,
        (ll)NH_ * S_ * S_, (ll)S_ * S_, NH_, 0.08838834764831845f);
    // our launch 8: softmax -> fp16 hi/lo probs (causal prefix only)
    softmax_split<<<B_ * NH_ * S_, 256>>>(Pf, Ph, Pl);
    // our launch 9: AV per (b,g): (8192x256, K truncated) -> scrambled fp16 (hi only)
    wgemm<2,2><<<dim3(1, 64, 16), 256, SMEM2>>>(
        Ph, Pl, vT1, nullptr, scrh, nullptr, S_, S_, S_, 0,
        (ll)NH_ * S_ * S_, (ll)4 * S_ * S_,
        (ll)2048 * 2048, (ll)FGD_ * S_,
        (ll)S_ * FH_, FGD_, G_, 1.0f);
    // our launch 10: out = scr @ Wo^T (4096x4096, K=8192), A single fp16
    wgemm<0,1><<<dim3(16, 32, 1), 256, SMEM1>>>(
        scrh, nullptr, Wo1, nullptr, out, nullptr, FH_, FH_, FH_, HID_,
        0, 0, 0, 0, 0, 0, 1, 1.0f);
}